// round 3
// baseline (speedup 1.0000x reference)
#include <cuda_runtime.h>

#define Eg 16384
#define Ng 4096
#define Dg 128
#define DD 16384

static __device__ float g_x1[Eg*256];
static __device__ float g_x2[Eg*256];
static __device__ float g_x3[Eg*Dg];
static __device__ float g_U[DD*Dg];
static __device__ float g_C3[Dg*Dg];
static __device__ float g_alpha[DD];
static __device__ float g_beta[DD];
static __device__ float g_mean[256];
static __device__ float g_rstd[256];
static __device__ float g_mx3[Dg];
static __device__ float g_rx3[Dg];
static __device__ float g_psum[16*256];
static __device__ float g_psq[16*256];
static __device__ float g_msgsum[Ng*Dg];
static __device__ float g_cnt[Ng];
static __device__ float g_mrelu[Ng*Dg];
static __device__ float g_gi[Ng*384];
static __device__ float g_gh[Ng*384];

// C[M,N] = A[M,K] @ B[N,K]^T (+bias). M%64==0, N%64==0, K%16==0.
__global__ __launch_bounds__(256) void gemm_tn(
    const float* __restrict__ A, const float* __restrict__ B,
    float* __restrict__ C, const float* __restrict__ bias,
    int M, int Nc, int K)
{
    __shared__ float sA[16][68];
    __shared__ float sB[16][68];
    int tid = threadIdx.x;
    int m0 = blockIdx.y * 64, n0 = blockIdx.x * 64;
    int tm = tid >> 4, tn = tid & 15;
    int row = tid >> 2, kq = tid & 3;
    float acc[4][4];
    #pragma unroll
    for (int i=0;i<4;++i)
        #pragma unroll
        for (int j=0;j<4;++j) acc[i][j]=0.f;
    for (int k0 = 0; k0 < K; k0 += 16) {
        float4 av = *(const float4*)&A[(size_t)(m0+row)*K + k0 + kq*4];
        float4 bv = *(const float4*)&B[(size_t)(n0+row)*K + k0 + kq*4];
        __syncthreads();
        sA[kq*4+0][row]=av.x; sA[kq*4+1][row]=av.y; sA[kq*4+2][row]=av.z; sA[kq*4+3][row]=av.w;
        sB[kq*4+0][row]=bv.x; sB[kq*4+1][row]=bv.y; sB[kq*4+2][row]=bv.z; sB[kq*4+3][row]=bv.w;
        __syncthreads();
        #pragma unroll
        for (int kk = 0; kk < 16; ++kk) {
            float4 a = *(const float4*)&sA[kk][tm*4];
            float4 b = *(const float4*)&sB[kk][tn*4];
            float aa[4]={a.x,a.y,a.z,a.w}, bb[4]={b.x,b.y,b.z,b.w};
            #pragma unroll
            for (int i=0;i<4;++i)
                #pragma unroll
                for (int j=0;j<4;++j) acc[i][j] += aa[i]*bb[j];
        }
    }
    #pragma unroll
    for (int i=0;i<4;++i) {
        float4 o = make_float4(acc[i][0],acc[i][1],acc[i][2],acc[i][3]);
        if (bias) { o.x+=bias[n0+tn*4]; o.y+=bias[n0+tn*4+1]; o.z+=bias[n0+tn*4+2]; o.w+=bias[n0+tn*4+3]; }
        *(float4*)&C[(size_t)(m0+tm*4+i)*Nc + n0 + tn*4] = o;
    }
}

__global__ __launch_bounds__(256) void colstats_partial(
    const float* __restrict__ Z, int M, int C,
    float* __restrict__ psum, float* __restrict__ psq)
{
    int lane = threadIdx.x & 31, w = threadIdx.x >> 5;
    int c = blockIdx.x*32 + lane;
    int rows = M / gridDim.y, r0 = blockIdx.y * rows;
    float s=0.f, q=0.f;
    for (int r = r0 + w; r < r0 + rows; r += 8) {
        float v = Z[(size_t)r*C + c];
        s += v; q += v*v;
    }
    __shared__ float ss[8][32], sq2[8][32];
    ss[w][lane]=s; sq2[w][lane]=q;
    __syncthreads();
    if (w == 0) {
        #pragma unroll
        for (int i=1;i<8;++i){ s+=ss[i][lane]; q+=sq2[i][lane]; }
        psum[blockIdx.y*C+c]=s; psq[blockIdx.y*C+c]=q;
    }
}

__global__ void colstats_final(int M, int C, int splits,
    const float* __restrict__ psum, const float* __restrict__ psq,
    float* __restrict__ mean, float* __restrict__ rstd)
{
    int c = blockIdx.x*blockDim.x + threadIdx.x;
    if (c >= C) return;
    float s=0.f, q=0.f;
    for (int i=0;i<splits;++i){ s+=psum[i*C+c]; q+=psq[i*C+c]; }
    float m = s/(float)M;
    mean[c]=m; rstd[c]=rsqrtf(q/(float)M - m*m + 1e-5f);
}

__global__ void bnrelu_kernel(float* __restrict__ Z,
    const float* __restrict__ mean, const float* __restrict__ rstd,
    const float* __restrict__ g, const float* __restrict__ b, int total, int cmask)
{
    int i = blockIdx.x*256 + threadIdx.x;
    if (i >= total) return;
    int c = i & cmask;
    Z[i] = fmaxf((Z[i]-mean[c])*rstd[c]*g[c] + b[c], 0.f);
}

// C3 = x3^T @ x3
__global__ __launch_bounds__(256) void syrk_x3()
{
    __shared__ float sAcc[8][1024];
    int tid = threadIdx.x, lane = tid & 31, w = tid >> 5;
    int i0 = blockIdx.x * 8;
    int seg = Eg / gridDim.y;
    int e0 = blockIdx.y * seg, e1 = e0 + seg;
    float acc[8][4];
    #pragma unroll
    for (int a=0;a<8;++a)
        #pragma unroll
        for (int b=0;b<4;++b) acc[a][b]=0.f;
    for (int e = e0 + w; e < e1; e += 8) {
        const float* row = g_x3 + (size_t)e*128;
        float4 xj  = *(const float4*)&row[lane*4];
        float4 xi0 = *(const float4*)&row[i0];
        float4 xi1 = *(const float4*)&row[i0+4];
        float xi[8]={xi0.x,xi0.y,xi0.z,xi0.w,xi1.x,xi1.y,xi1.z,xi1.w};
        float xv[4]={xj.x,xj.y,xj.z,xj.w};
        #pragma unroll
        for (int a=0;a<8;++a)
            #pragma unroll
            for (int b=0;b<4;++b) acc[a][b]+=xi[a]*xv[b];
    }
    #pragma unroll
    for (int a=0;a<8;++a)
        *(float4*)&sAcc[w][a*128+lane*4]=make_float4(acc[a][0],acc[a][1],acc[a][2],acc[a][3]);
    __syncthreads();
    for (int o = tid; o < 1024; o += 256) {
        float s=0.f;
        #pragma unroll
        for (int ww=0;ww<8;++ww) s+=sAcc[ww][o];
        atomicAdd(&g_C3[(i0+(o>>7))*128 + (o&127)], s);
    }
}

__global__ void alphabeta_kernel(const float* __restrict__ W4,
    const float* __restrict__ g4, const float* __restrict__ b4)
{
    int c = blockIdx.x*blockDim.x + threadIdx.x;
    const float4* w = (const float4*)(W4 + (size_t)c*128);
    const float4* u = (const float4*)(g_U + (size_t)c*128);
    const float4* mx = (const float4*)g_mx3;
    float m4=0.f, q=0.f;
    #pragma unroll 8
    for (int i=0;i<32;++i) {
        float4 wv=w[i], uv=u[i], mv=mx[i];
        m4 += wv.x*mv.x + wv.y*mv.y + wv.z*mv.z + wv.w*mv.w;
        q  += wv.x*uv.x + wv.y*uv.y + wv.z*uv.z + wv.w*uv.w;
    }
    float var = q*(1.0f/(float)Eg) - m4*m4;
    float a = g4[c]*rsqrtf(var + 1e-5f);
    g_alpha[c]=a; g_beta[c]=b4[c]-m4*a;
}

__global__ void zero_kernel()
{
    int i = blockIdx.x*256 + threadIdx.x;
    if (i < Ng*Dg) g_msgsum[i]=0.f;
    if (i < Ng)    g_cnt[i]=0.f;
    if (i < Dg*Dg) g_C3[i]=0.f;
}

__global__ void cnt_kernel(const int* __restrict__ ei)
{
    int e = blockIdx.x*256 + threadIdx.x;
    if (e < Eg) atomicAdd(&g_cnt[ei[2*e+1]], 1.0f);
}

// msg[e,k] = sum_{d,j} xi[e,d]*x3[e,j]*alpha[dk]*W4[dk,j] + sum_d xi[e,d]*beta[dk]
__global__ __launch_bounds__(256,1) void big_msg_kernel(
    const float* __restrict__ node, const int* __restrict__ ei,
    const float* __restrict__ W4)
{
    extern __shared__ float sm[];
    float* sXi = sm;                 // [128][132] xi^T
    float* sX3 = sm + 128*132;       // [128][132] x3^T
    float* sW  = sm + 2*128*132;     // [32][132]
    __shared__ int sSrc[128], sDst[128];
    int tid = threadIdx.x;
    int e0 = blockIdx.x * 128;
    if (tid < 128) { sSrc[tid]=ei[2*(e0+tid)]; sDst[tid]=ei[2*(e0+tid)+1]; }
    __syncthreads();
    #pragma unroll
    for (int i=0;i<16;++i) {
        int u = tid + i*256, e = u>>5, f = u&31;
        float4 v = *(const float4*)&node[(size_t)sSrc[e]*128 + f*4];
        sXi[(f*4+0)*132+e]=v.x; sXi[(f*4+1)*132+e]=v.y; sXi[(f*4+2)*132+e]=v.z; sXi[(f*4+3)*132+e]=v.w;
        float4 t = *(const float4*)&g_x3[(size_t)(e0+e)*128 + f*4];
        sX3[(f*4+0)*132+e]=t.x; sX3[(f*4+1)*132+e]=t.y; sX3[(f*4+2)*132+e]=t.z; sX3[(f*4+3)*132+e]=t.w;
    }
    __syncthreads();
    int te = tid >> 4, tk = tid & 15;
    int eb = te*8, kb = tk*8;
    float acc[8][8];
    #pragma unroll
    for (int p=0;p<8;++p)
        #pragma unroll
        for (int q=0;q<8;++q) acc[p][q]=0.f;

    for (int d = 0; d < 128; ++d) {
        float4 xa = *(const float4*)&sXi[d*132+eb];
        float4 xb = *(const float4*)&sXi[d*132+eb+4];
        float xiv[8]={xa.x,xa.y,xa.z,xa.w,xb.x,xb.y,xb.z,xb.w};
        for (int jc = 0; jc < 4; ++jc) {
            __syncthreads();
            #pragma unroll
            for (int i=0;i<4;++i) {
                int u = tid + i*256, k = u>>3, jg = u&7;
                float a = g_alpha[d*128+k];
                float4 v = *(const float4*)&W4[(size_t)(d*128+k)*128 + jc*32 + jg*4];
                sW[(jg*4+0)*132+k]=a*v.x; sW[(jg*4+1)*132+k]=a*v.y;
                sW[(jg*4+2)*132+k]=a*v.z; sW[(jg*4+3)*132+k]=a*v.w;
            }
            __syncthreads();
            #pragma unroll 4
            for (int jj = 0; jj < 32; ++jj) {
                int j = jc*32 + jj;
                float4 x3a = *(const float4*)&sX3[j*132+eb];
                float4 x3b = *(const float4*)&sX3[j*132+eb+4];
                float av[8];
                av[0]=xiv[0]*x3a.x; av[1]=xiv[1]*x3a.y; av[2]=xiv[2]*x3a.z; av[3]=xiv[3]*x3a.w;
                av[4]=xiv[4]*x3b.x; av[5]=xiv[5]*x3b.y; av[6]=xiv[6]*x3b.z; av[7]=xiv[7]*x3b.w;
                float4 w0 = *(const float4*)&sW[jj*132+kb];
                float4 w1 = *(const float4*)&sW[jj*132+kb+4];
                float wv[8]={w0.x,w0.y,w0.z,w0.w,w1.x,w1.y,w1.z,w1.w};
                #pragma unroll
                for (int p=0;p<8;++p)
                    #pragma unroll
                    for (int q=0;q<8;++q) acc[p][q] += av[p]*wv[q];
            }
        }
    }
    // beta term
    for (int dc = 0; dc < 4; ++dc) {
        __syncthreads();
        #pragma unroll
        for (int i=0;i<4;++i) {
            int u = tid + i*256, dd = u>>5, f = u&31;
            float4 v = *(const float4*)&g_beta[(size_t)(dc*32+dd)*128 + f*4];
            *(float4*)&sW[dd*132 + f*4] = v;
        }
        __syncthreads();
        #pragma unroll 4
        for (int dd = 0; dd < 32; ++dd) {
            int d = dc*32 + dd;
            float4 xa = *(const float4*)&sXi[d*132+eb];
            float4 xb = *(const float4*)&sXi[d*132+eb+4];
            float av[8]={xa.x,xa.y,xa.z,xa.w,xb.x,xb.y,xb.z,xb.w};
            float4 w0 = *(const float4*)&sW[dd*132+kb];
            float4 w1 = *(const float4*)&sW[dd*132+kb+4];
            float wv[8]={w0.x,w0.y,w0.z,w0.w,w1.x,w1.y,w1.z,w1.w};
            #pragma unroll
            for (int p=0;p<8;++p)
                #pragma unroll
                for (int q=0;q<8;++q) acc[p][q] += av[p]*wv[q];
        }
    }
    #pragma unroll
    for (int p=0;p<8;++p) {
        float* out = g_msgsum + (size_t)sDst[eb+p]*128 + kb;
        #pragma unroll
        for (int q=0;q<8;++q) atomicAdd(&out[q], acc[p][q]);
    }
}

__global__ void finalize_msg(const float* __restrict__ bias)
{
    int i = blockIdx.x*256 + threadIdx.x;
    if (i >= Ng*Dg) return;
    float c = fmaxf(g_cnt[i>>7], 1.0f);
    g_mrelu[i] = fmaxf(g_msgsum[i]/c + bias[i&127], 0.0f);
}

__global__ void gru_kernel(const float* __restrict__ h0, float* __restrict__ out, int twice)
{
    int i = blockIdx.x*256 + threadIdx.x;
    if (i >= Ng*Dg) return;
    int n = i>>7, k = i&127;
    const float* gir = g_gi + (size_t)n*384;
    const float* ghr = g_gh + (size_t)n*384;
    float r = 1.f/(1.f + expf(-(gir[k]     + ghr[k])));
    float z = 1.f/(1.f + expf(-(gir[128+k] + ghr[128+k])));
    float nn = tanhf(gir[256+k] + r*ghr[256+k]);
    float hn = (1.f - z)*nn + z*h0[i];
    out[i] = hn;
    if (twice) out[Ng*Dg + i] = hn;
}

static float* sym(const void* s) { void* p=0; cudaGetSymbolAddress(&p, s); return (float*)p; }

extern "C" void kernel_launch(void* const* d_in, const int* in_sizes, int n_in,
                              void* d_out, int out_size)
{
    const float* node   = (const float*)d_in[0];
    const int*   ei     = (const int*)  d_in[1];
    const float* edge   = (const float*)d_in[2];
    const float* hidden = (const float*)d_in[3];
    const float* W1=(const float*)d_in[4],  *g1=(const float*)d_in[5],  *b1=(const float*)d_in[6];
    const float* W2=(const float*)d_in[7],  *g2=(const float*)d_in[8],  *b2=(const float*)d_in[9];
    const float* W3=(const float*)d_in[10], *g3=(const float*)d_in[11], *b3=(const float*)d_in[12];
    const float* W4=(const float*)d_in[13];
    const float* g4=(const float*)d_in[14], *b4=(const float*)d_in[15];
    const float* bias=(const float*)d_in[16];
    const float* W_ih=(const float*)d_in[17], *W_hh=(const float*)d_in[18];
    const float* b_ih=(const float*)d_in[19], *b_hh=(const float*)d_in[20];
    (void)in_sizes; (void)n_in;

    float *x1=sym(g_x1), *x2=sym(g_x2), *x3=sym(g_x3);
    float *U=sym(g_U), *C3=sym(g_C3);
    float *mn=sym(g_mean), *rs=sym(g_rstd);
    float *ps=sym(g_psum), *pq=sym(g_psq);
    float *mx3=sym(g_mx3), *rx3=sym(g_rx3);
    float *mr=sym(g_mrelu), *gi=sym(g_gi), *gh=sym(g_gh);

    zero_kernel<<<2048,256>>>();

    gemm_tn<<<dim3(4,256),256>>>(edge, W1, x1, nullptr, Eg, 256, 16);
    colstats_partial<<<dim3(8,16),256>>>(x1, Eg, 256, ps, pq);
    colstats_final<<<1,256>>>(Eg, 256, 16, ps, pq, mn, rs);
    bnrelu_kernel<<<Eg,256>>>(x1, mn, rs, g1, b1, Eg*256, 255);

    gemm_tn<<<dim3(4,256),256>>>(x1, W2, x2, nullptr, Eg, 256, 256);
    colstats_partial<<<dim3(8,16),256>>>(x2, Eg, 256, ps, pq);
    colstats_final<<<1,256>>>(Eg, 256, 16, ps, pq, mn, rs);
    bnrelu_kernel<<<Eg,256>>>(x2, mn, rs, g2, b2, Eg*256, 255);

    gemm_tn<<<dim3(2,256),256>>>(x2, W3, x3, nullptr, Eg, 128, 256);
    colstats_partial<<<dim3(4,16),256>>>(x3, Eg, 128, ps, pq);
    colstats_final<<<1,128>>>(Eg, 128, 16, ps, pq, mn, rs);
    bnrelu_kernel<<<Eg/2,256>>>(x3, mn, rs, g3, b3, Eg*128, 127);

    // stats of FINAL x3 for BN4 closed form
    colstats_partial<<<dim3(4,16),256>>>(x3, Eg, 128, ps, pq);
    colstats_final<<<1,128>>>(Eg, 128, 16, ps, pq, mx3, rx3);
    syrk_x3<<<dim3(16,32),256>>>();
    gemm_tn<<<dim3(2,256),256>>>(W4, C3, U, nullptr, DD, 128, 128);
    alphabeta_kernel<<<64,256>>>(W4, g4, b4);

    cnt_kernel<<<64,256>>>(ei);

    cudaFuncSetAttribute(big_msg_kernel, cudaFuncAttributeMaxDynamicSharedMemorySize, 152064);
    big_msg_kernel<<<128,256,152064>>>(node, ei, W4);

    finalize_msg<<<2048,256>>>(bias);

    gemm_tn<<<dim3(6,64),256>>>(mr,     W_ih, gi, b_ih, Ng, 384, 128);
    gemm_tn<<<dim3(6,64),256>>>(hidden, W_hh, gh, b_hh, Ng, 384, 128);

    int twice = (out_size >= 2*Ng*Dg) ? 1 : 0;
    gru_kernel<<<2048,256>>>(hidden, (float*)d_out, twice);
}

// round 5
// speedup vs baseline: 2.5504x; 2.5504x over previous
#include <cuda_runtime.h>
#include <cuda_bf16.h>
#include <cstdint>

#define Eg 16384
#define Ng 4096
#define Dg 128
#define DD 16384

static __device__ float g_x1[Eg*256];
static __device__ float g_x2[Eg*256];
static __device__ float g_x3[Eg*Dg];
static __device__ float g_U[DD*Dg];
static __device__ float g_C3[Dg*Dg];
static __device__ float g_alpha[DD];
static __device__ float g_betaT[Dg*Dg];
static __device__ float g_mean[256];
static __device__ float g_rstd[256];
static __device__ float g_mx3[Dg];
static __device__ float g_rx3[Dg];
static __device__ float g_psum[16*256];
static __device__ float g_psq[16*256];
static __device__ float g_msgsum[Ng*Dg];
static __device__ float g_S[Ng*Dg];
static __device__ float g_sbeta[Ng*Dg];
static __device__ float g_cnt[Ng];
static __device__ float g_mrelu[Ng*Dg];
static __device__ float g_gi[Ng*384];
static __device__ float g_gh[Ng*384];
static __device__ unsigned short g_Gh[DD*128];
static __device__ unsigned short g_Gl[DD*128];

// ---------- helpers (all base-sm_100 legal) ----------
__device__ __forceinline__ uint32_t smem_u32(const void* p) {
    uint32_t a;
    asm("{ .reg .u64 t; cvta.to.shared.u64 t, %1; cvt.u32.u64 %0, t; }" : "=r"(a) : "l"(p));
    return a;
}
__device__ __forceinline__ void mma_bf16(float* d, const uint32_t* a, const uint32_t* b, const float* c) {
    asm volatile("mma.sync.aligned.m16n8k16.row.col.f32.bf16.bf16.f32 "
        "{%0,%1,%2,%3}, {%4,%5,%6,%7}, {%8,%9}, {%10,%11,%12,%13};"
        : "=f"(d[0]),"=f"(d[1]),"=f"(d[2]),"=f"(d[3])
        : "r"(a[0]),"r"(a[1]),"r"(a[2]),"r"(a[3]), "r"(b[0]),"r"(b[1]),
          "f"(c[0]),"f"(c[1]),"f"(c[2]),"f"(c[3]));
}
__device__ __forceinline__ void ldsm4(uint32_t* r, uint32_t addr) {
    asm volatile("ldmatrix.sync.aligned.m8n8.x4.shared.b16 {%0,%1,%2,%3}, [%4];"
        : "=r"(r[0]),"=r"(r[1]),"=r"(r[2]),"=r"(r[3]) : "r"(addr));
}
__device__ __forceinline__ void cp16(uint32_t dst, const void* src) {
    asm volatile("cp.async.cg.shared.global [%0], [%1], 16;" :: "r"(dst), "l"(src));
}
#define CP_COMMIT() asm volatile("cp.async.commit_group;" ::: "memory")

// ---------- generic fp32 GEMM (side ops): C[M,N]=A[M,K]@B[N,K]^T (+bias) ----------
__global__ __launch_bounds__(256) void gemm_tn(
    const float* __restrict__ A, const float* __restrict__ B,
    float* __restrict__ C, const float* __restrict__ bias, int M, int Nc, int K)
{
    __shared__ float sA[16][68], sB[16][68];
    int tid = threadIdx.x;
    int m0 = blockIdx.y*64, n0 = blockIdx.x*64;
    int tm = tid>>4, tn = tid&15, row = tid>>2, kq = tid&3;
    float acc[4][4];
    #pragma unroll
    for (int i=0;i<4;++i) { acc[i][0]=0;acc[i][1]=0;acc[i][2]=0;acc[i][3]=0; }
    for (int k0=0;k0<K;k0+=16) {
        float4 av = *(const float4*)&A[(size_t)(m0+row)*K + k0 + kq*4];
        float4 bv = *(const float4*)&B[(size_t)(n0+row)*K + k0 + kq*4];
        __syncthreads();
        sA[kq*4+0][row]=av.x; sA[kq*4+1][row]=av.y; sA[kq*4+2][row]=av.z; sA[kq*4+3][row]=av.w;
        sB[kq*4+0][row]=bv.x; sB[kq*4+1][row]=bv.y; sB[kq*4+2][row]=bv.z; sB[kq*4+3][row]=bv.w;
        __syncthreads();
        #pragma unroll
        for (int kk=0;kk<16;++kk) {
            float4 a = *(const float4*)&sA[kk][tm*4];
            float4 b = *(const float4*)&sB[kk][tn*4];
            float aa[4]={a.x,a.y,a.z,a.w}, bb[4]={b.x,b.y,b.z,b.w};
            #pragma unroll
            for (int i=0;i<4;++i)
                #pragma unroll
                for (int j=0;j<4;++j) acc[i][j] += aa[i]*bb[j];
        }
    }
    #pragma unroll
    for (int i=0;i<4;++i) {
        float4 o = make_float4(acc[i][0],acc[i][1],acc[i][2],acc[i][3]);
        if (bias) { o.x+=bias[n0+tn*4]; o.y+=bias[n0+tn*4+1]; o.z+=bias[n0+tn*4+2]; o.w+=bias[n0+tn*4+3]; }
        *(float4*)&C[(size_t)(m0+tm*4+i)*Nc + n0 + tn*4] = o;
    }
}

__global__ __launch_bounds__(256) void colstats_partial(
    const float* __restrict__ Z, int M, int C, float* __restrict__ psum, float* __restrict__ psq)
{
    int lane = threadIdx.x & 31, w = threadIdx.x >> 5;
    int c = blockIdx.x*32 + lane;
    int rows = M/gridDim.y, r0 = blockIdx.y*rows;
    float s=0.f, q=0.f;
    for (int r=r0+w; r<r0+rows; r+=8) { float v=Z[(size_t)r*C+c]; s+=v; q+=v*v; }
    __shared__ float ss[8][32], sq2[8][32];
    ss[w][lane]=s; sq2[w][lane]=q;
    __syncthreads();
    if (w==0) {
        #pragma unroll
        for (int i=1;i<8;++i){ s+=ss[i][lane]; q+=sq2[i][lane]; }
        psum[blockIdx.y*C+c]=s; psq[blockIdx.y*C+c]=q;
    }
}
__global__ void colstats_final(int M, int C, int splits,
    const float* __restrict__ psum, const float* __restrict__ psq,
    float* __restrict__ mean, float* __restrict__ rstd)
{
    int c = blockIdx.x*blockDim.x + threadIdx.x;
    if (c >= C) return;
    float s=0.f,q=0.f;
    for (int i=0;i<splits;++i){ s+=psum[i*C+c]; q+=psq[i*C+c]; }
    float m = s/(float)M;
    mean[c]=m; rstd[c]=rsqrtf(q/(float)M - m*m + 1e-5f);
}
__global__ void bnrelu_kernel(float* __restrict__ Z,
    const float* __restrict__ mean, const float* __restrict__ rstd,
    const float* __restrict__ g, const float* __restrict__ b, int total, int cmask)
{
    int i = blockIdx.x*256 + threadIdx.x;
    if (i >= total) return;
    int c = i & cmask;
    Z[i] = fmaxf((Z[i]-mean[c])*rstd[c]*g[c] + b[c], 0.f);
}
__global__ __launch_bounds__(256) void syrk_x3()
{
    __shared__ float sAcc[8][1024];
    int tid = threadIdx.x, lane = tid&31, w = tid>>5;
    int i0 = blockIdx.x*8;
    int seg = Eg/gridDim.y, e0 = blockIdx.y*seg, e1 = e0+seg;
    float acc[8][4];
    #pragma unroll
    for (int a=0;a<8;++a){acc[a][0]=0;acc[a][1]=0;acc[a][2]=0;acc[a][3]=0;}
    for (int e=e0+w; e<e1; e+=8) {
        const float* row = g_x3 + (size_t)e*128;
        float4 xj = *(const float4*)&row[lane*4];
        float4 x0 = *(const float4*)&row[i0];
        float4 x1 = *(const float4*)&row[i0+4];
        float xi[8]={x0.x,x0.y,x0.z,x0.w,x1.x,x1.y,x1.z,x1.w};
        float xv[4]={xj.x,xj.y,xj.z,xj.w};
        #pragma unroll
        for (int a=0;a<8;++a)
            #pragma unroll
            for (int b=0;b<4;++b) acc[a][b]+=xi[a]*xv[b];
    }
    #pragma unroll
    for (int a=0;a<8;++a)
        *(float4*)&sAcc[w][a*128+lane*4]=make_float4(acc[a][0],acc[a][1],acc[a][2],acc[a][3]);
    __syncthreads();
    for (int o=tid;o<1024;o+=256) {
        float s=0.f;
        #pragma unroll
        for (int ww=0;ww<8;++ww) s+=sAcc[ww][o];
        atomicAdd(&g_C3[(i0+(o>>7))*128 + (o&127)], s);
    }
}
__global__ void alphabeta_kernel(const float* __restrict__ W4,
    const float* __restrict__ g4, const float* __restrict__ b4)
{
    int c = blockIdx.x*blockDim.x + threadIdx.x;
    const float4* w = (const float4*)(W4 + (size_t)c*128);
    const float4* u = (const float4*)(g_U + (size_t)c*128);
    const float4* mx = (const float4*)g_mx3;
    float m4=0.f, q=0.f;
    #pragma unroll 8
    for (int i=0;i<32;++i) {
        float4 wv=w[i], uv=u[i], mv=mx[i];
        m4 += wv.x*mv.x + wv.y*mv.y + wv.z*mv.z + wv.w*mv.w;
        q  += wv.x*uv.x + wv.y*uv.y + wv.z*uv.z + wv.w*uv.w;
    }
    float var = q*(1.0f/(float)Eg) - m4*m4;
    float a = g4[c]*rsqrtf(var + 1e-5f);
    g_alpha[c]=a;
    g_betaT[(c&127)*128 + (c>>7)] = b4[c]-m4*a;   // betaT[k][d]
}
// split G = alpha * W4 into bf16 hi/lo
__global__ void gsplit_kernel(const float* __restrict__ W4)
{
    int idx = blockIdx.x*256 + threadIdx.x;   // < DD*128
    int c = idx >> 7;
    float v = g_alpha[c] * W4[idx];
    uint32_t u = __float_as_uint(v);
    g_Gh[idx] = (unsigned short)(u >> 16);
    float lo = v - __uint_as_float(u & 0xFFFF0000u);
    __nv_bfloat16 lb = __float2bfloat16_rn(lo);
    g_Gl[idx] = *(unsigned short*)&lb;
}
__global__ void zero_kernel()
{
    int i = blockIdx.x*256 + threadIdx.x;
    if (i < Ng*Dg) { g_msgsum[i]=0.f; g_S[i]=0.f; }
    if (i < Ng)    g_cnt[i]=0.f;
    if (i < Dg*Dg) g_C3[i]=0.f;
}
__global__ void cnt_kernel(const int* __restrict__ ei)
{
    int e = blockIdx.x*256 + threadIdx.x;
    if (e < Eg) atomicAdd(&g_cnt[ei[2*e+1]], 1.0f);
}
__global__ void ssum_kernel(const int* __restrict__ ei, const float* __restrict__ node)
{
    int idx = blockIdx.x*256 + threadIdx.x;
    if (idx >= Eg*128) return;
    int e = idx>>7, k = idx&127;
    atomicAdd(&g_S[(size_t)ei[2*e+1]*128 + k], node[(size_t)ei[2*e]*128 + k]);
}

// ---------- big fused GEMM: V'_d = x3_tile @ G_d^T, msg += xi[:,d] * V'_d ----------
#define ROWB   272                   // padded SMEM row stride (bytes) for G tiles
#define BUF_SPLIT (128*ROWB)         // 34816 per split (hi or lo)
#define BUF_SIZE  (2*BUF_SPLIT)      // 69632 per buffer
#define XIT_OFF   (2*BUF_SIZE)       // 139264
#define BIG_SMEM  (XIT_OFF + 65536)  // 204800

__device__ __forceinline__ void load_G(int d, int tid, uint32_t smem_base) {
    const char* GH = (const char*)g_Gh;
    const char* GL = (const char*)g_Gl;
    uint32_t bufb = smem_base + (d&1)*BUF_SIZE;
    #pragma unroll
    for (int i=0;i<16;++i) {
        int q = tid + i*256;
        int split = q>>11, row = (q>>4)&127, c16 = q&15;
        const char* src = (split? GL : GH) + ((size_t)d*128 + row)*256 + c16*16;
        uint32_t dst = bufb + split*BUF_SPLIT + row*ROWB + c16*16;
        cp16(dst, src);
    }
    CP_COMMIT();
}

__global__ __launch_bounds__(256,1) void big_msg_kernel(
    const float* __restrict__ node, const int* __restrict__ ei)
{
    extern __shared__ char sm[];
    float* xiT = (float*)(sm + XIT_OFF);   // [128 d][128 e]
    __shared__ int sDst[128];
    int tid = threadIdx.x, l = tid&31, w = tid>>5;
    int e0 = blockIdx.x*128;

    // indices + xi gather (transposed)
    {
        int e = tid>>1, hf = tid&1;
        int src = ei[2*(e0+e)];
        if (hf==0) sDst[e] = ei[2*(e0+e)+1];
        const float* nr = node + (size_t)src*128 + hf*64;
        #pragma unroll
        for (int i=0;i<16;++i) {
            float4 v = *(const float4*)&nr[i*4];
            int d = hf*64 + i*4;
            xiT[(d+0)*128+e]=v.x; xiT[(d+1)*128+e]=v.y; xiT[(d+2)*128+e]=v.z; xiT[(d+3)*128+e]=v.w;
        }
    }
    // stage x3 tile fp32 into (not-yet-used) buffer region
    float* sx3 = (float*)sm;   // [128 e][128 j]
    {
        const float* xr = g_x3 + (size_t)e0*128;
        #pragma unroll
        for (int i=0;i<16;++i) {
            int u = tid + i*256;
            *(float4*)&sx3[u*4] = *(const float4*)&xr[u*4];
        }
    }
    __syncthreads();

    // build register-resident A fragments (bf16 hi/lo, m16n8k16 layout)
    int ew = w*16;
    int r = l>>2, cq = (l&3)*2;
    uint32_t Ah[8][4], Al[8][4];
    {
        const float* Xr0 = sx3 + (size_t)(ew + r)*128;
        const float* Xr1 = sx3 + (size_t)(ew + r + 8)*128;
        #pragma unroll
        for (int jt=0;jt<8;++jt) {
            int c0 = jt*16 + cq;
            float2 p[4];
            p[0] = *(const float2*)&Xr0[c0];       // a0: (r,   c)
            p[1] = *(const float2*)&Xr1[c0];       // a1: (r+8, c)
            p[2] = *(const float2*)&Xr0[c0+8];     // a2: (r,   c+8)
            p[3] = *(const float2*)&Xr1[c0+8];     // a3: (r+8, c+8)
            #pragma unroll
            for (int q=0;q<4;++q) {
                uint32_t u0=__float_as_uint(p[q].x), u1=__float_as_uint(p[q].y);
                Ah[jt][q] = __byte_perm(u0,u1,0x7632);
                float h0=__uint_as_float(u0&0xFFFF0000u), h1=__uint_as_float(u1&0xFFFF0000u);
                __nv_bfloat162 lo2 = __floats2bfloat162_rn(p[q].x-h0, p[q].y-h1);
                Al[jt][q] = *(uint32_t*)&lo2;
            }
        }
    }
    __syncthreads();   // sx3 dead; buffers free for cp.async

    uint32_t smem_base = smem_u32(sm);
    // per-lane ldmatrix offset: blocks (n0,j0),(n0,j0+8),(n0+8,j0),(n0+8,j0+8)
    int ln = ((l>>4)&1)*8 + (l&7);
    int colsel = (l>>3)&1;
    uint32_t laneoff = (uint32_t)ln*ROWB + colsel*16;

    float msg[16][4];
    #pragma unroll
    for (int nt=0;nt<16;++nt) { msg[nt][0]=0;msg[nt][1]=0;msg[nt][2]=0;msg[nt][3]=0; }

    load_G(0, tid, smem_base);

    for (int d = 0; d < 128; ++d) {
        if (d < 127) {
            load_G(d+1, tid, smem_base);
            asm volatile("cp.async.wait_group 1;" ::: "memory");
        } else {
            asm volatile("cp.async.wait_group 0;" ::: "memory");
        }
        __syncthreads();

        uint32_t bufb = smem_base + (d&1)*BUF_SIZE;
        uint32_t aH = bufb + laneoff;
        uint32_t aL = bufb + BUF_SPLIT + laneoff;
        float xi0 = xiT[d*128 + ew + r];
        float xi1 = xiT[d*128 + ew + r + 8];

        #pragma unroll
        for (int ntp = 0; ntp < 8; ++ntp) {
            float v[8] = {0,0,0,0,0,0,0,0};
            uint32_t rowoff = (uint32_t)ntp*16*ROWB;
            #pragma unroll
            for (int jt = 0; jt < 8; ++jt) {
                uint32_t bh[4], bl[4];
                ldsm4(bh, aH + rowoff + jt*32);
                ldsm4(bl, aL + rowoff + jt*32);
                mma_bf16(v,   Ah[jt], bh,   v);
                mma_bf16(v,   Ah[jt], bl,   v);
                mma_bf16(v,   Al[jt], bh,   v);
                mma_bf16(v+4, Ah[jt], bh+2, v+4);
                mma_bf16(v+4, Ah[jt], bl+2, v+4);
                mma_bf16(v+4, Al[jt], bh+2, v+4);
            }
            msg[2*ntp  ][0] += xi0*v[0];
            msg[2*ntp  ][1] += xi0*v[1];
            msg[2*ntp  ][2] += xi1*v[2];
            msg[2*ntp  ][3] += xi1*v[3];
            msg[2*ntp+1][0] += xi0*v[4];
            msg[2*ntp+1][1] += xi0*v[5];
            msg[2*ntp+1][2] += xi1*v[6];
            msg[2*ntp+1][3] += xi1*v[7];
        }
        __syncthreads();   // protect buffer (d+1)&1 from next prefetch
    }

    // scatter segment-sum
    int d0 = sDst[ew + r], d1 = sDst[ew + r + 8];
    #pragma unroll
    for (int nt = 0; nt < 16; ++nt) {
        int k = nt*8 + cq;
        atomicAdd(&g_msgsum[(size_t)d0*128 + k],     msg[nt][0]);
        atomicAdd(&g_msgsum[(size_t)d0*128 + k + 1], msg[nt][1]);
        atomicAdd(&g_msgsum[(size_t)d1*128 + k],     msg[nt][2]);
        atomicAdd(&g_msgsum[(size_t)d1*128 + k + 1], msg[nt][3]);
    }
}

__global__ void finalize_msg(const float* __restrict__ bias)
{
    int i = blockIdx.x*256 + threadIdx.x;
    if (i >= Ng*Dg) return;
    float c = fmaxf(g_cnt[i>>7], 1.0f);
    g_mrelu[i] = fmaxf((g_msgsum[i] + g_sbeta[i])/c + bias[i&127], 0.0f);
}
__global__ void gru_kernel(const float* __restrict__ h0, float* __restrict__ out, int twice)
{
    int i = blockIdx.x*256 + threadIdx.x;
    if (i >= Ng*Dg) return;
    int n = i>>7, k = i&127;
    const float* gir = g_gi + (size_t)n*384;
    const float* ghr = g_gh + (size_t)n*384;
    float r = 1.f/(1.f + expf(-(gir[k]     + ghr[k])));
    float z = 1.f/(1.f + expf(-(gir[128+k] + ghr[128+k])));
    float nn = tanhf(gir[256+k] + r*ghr[256+k]);
    float hn = (1.f - z)*nn + z*h0[i];
    out[i] = hn;
    if (twice) out[Ng*Dg + i] = hn;
}

static float* sym(const void* s) { void* p=0; cudaGetSymbolAddress(&p, s); return (float*)p; }

extern "C" void kernel_launch(void* const* d_in, const int* in_sizes, int n_in,
                              void* d_out, int out_size)
{
    const float* node   = (const float*)d_in[0];
    const int*   ei     = (const int*)  d_in[1];
    const float* edge   = (const float*)d_in[2];
    const float* hidden = (const float*)d_in[3];
    const float* W1=(const float*)d_in[4],  *g1=(const float*)d_in[5],  *b1=(const float*)d_in[6];
    const float* W2=(const float*)d_in[7],  *g2=(const float*)d_in[8],  *b2=(const float*)d_in[9];
    const float* W3=(const float*)d_in[10], *g3=(const float*)d_in[11], *b3=(const float*)d_in[12];
    const float* W4=(const float*)d_in[13];
    const float* g4=(const float*)d_in[14], *b4=(const float*)d_in[15];
    const float* bias=(const float*)d_in[16];
    const float* W_ih=(const float*)d_in[17], *W_hh=(const float*)d_in[18];
    const float* b_ih=(const float*)d_in[19], *b_hh=(const float*)d_in[20];
    (void)in_sizes; (void)n_in;

    float *x1=sym(g_x1), *x2=sym(g_x2), *x3=sym(g_x3);
    float *U=sym(g_U), *C3=sym(g_C3);
    float *mn=sym(g_mean), *rs=sym(g_rstd);
    float *ps=sym(g_psum), *pq=sym(g_psq);
    float *mx3=sym(g_mx3), *rx3=sym(g_rx3);
    float *mr=sym(g_mrelu), *gi=sym(g_gi), *gh=sym(g_gh);
    float *S=sym(g_S), *bT=sym(g_betaT), *sb=sym(g_sbeta);

    zero_kernel<<<2048,256>>>();

    gemm_tn<<<dim3(4,256),256>>>(edge, W1, x1, nullptr, Eg, 256, 16);
    colstats_partial<<<dim3(8,16),256>>>(x1, Eg, 256, ps, pq);
    colstats_final<<<1,256>>>(Eg, 256, 16, ps, pq, mn, rs);
    bnrelu_kernel<<<Eg,256>>>(x1, mn, rs, g1, b1, Eg*256, 255);

    gemm_tn<<<dim3(4,256),256>>>(x1, W2, x2, nullptr, Eg, 256, 256);
    colstats_partial<<<dim3(8,16),256>>>(x2, Eg, 256, ps, pq);
    colstats_final<<<1,256>>>(Eg, 256, 16, ps, pq, mn, rs);
    bnrelu_kernel<<<Eg,256>>>(x2, mn, rs, g2, b2, Eg*256, 255);

    gemm_tn<<<dim3(2,256),256>>>(x2, W3, x3, nullptr, Eg, 128, 256);
    colstats_partial<<<dim3(4,16),256>>>(x3, Eg, 128, ps, pq);
    colstats_final<<<1,128>>>(Eg, 128, 16, ps, pq, mn, rs);
    bnrelu_kernel<<<Eg/2,256>>>(x3, mn, rs, g3, b3, Eg*128, 127);

    colstats_partial<<<dim3(4,16),256>>>(x3, Eg, 128, ps, pq);
    colstats_final<<<1,128>>>(Eg, 128, 16, ps, pq, mx3, rx3);
    syrk_x3<<<dim3(16,32),256>>>();
    gemm_tn<<<dim3(2,256),256>>>(W4, C3, U, nullptr, DD, 128, 128);
    alphabeta_kernel<<<64,256>>>(W4, g4, b4);
    gsplit_kernel<<<DD*128/256,256>>>(W4);

    cnt_kernel<<<64,256>>>(ei);
    ssum_kernel<<<Eg*128/256,256>>>(ei, node);

    cudaFuncSetAttribute(big_msg_kernel, cudaFuncAttributeMaxDynamicSharedMemorySize, BIG_SMEM);
    big_msg_kernel<<<128,256,BIG_SMEM>>>(node, ei);

    gemm_tn<<<dim3(2,64),256>>>(S, bT, sb, nullptr, Ng, 128, 128);
    finalize_msg<<<2048,256>>>(bias);

    gemm_tn<<<dim3(6,64),256>>>(mr,     W_ih, gi, b_ih, Ng, 384, 128);
    gemm_tn<<<dim3(6,64),256>>>(hidden, W_hh, gh, b_hh, Ng, 384, 128);

    int twice = (out_size >= 2*Ng*Dg) ? 1 : 0;
    gru_kernel<<<2048,256>>>(hidden, (float*)d_out, twice);
}

// round 6
// speedup vs baseline: 3.1137x; 1.2209x over previous
#include <cuda_runtime.h>
#include <cuda_bf16.h>
#include <cuda_fp16.h>
#include <cstdint>

#define Eg 16384
#define Ng 4096
#define Dg 128
#define DD 16384

static __device__ float g_x1[Eg*256];
static __device__ float g_x2[Eg*256];
static __device__ float g_x3[Eg*Dg];
static __device__ float g_U[DD*Dg];
static __device__ float g_C3[Dg*Dg];
static __device__ float g_alpha[DD];
static __device__ float g_betaT[Dg*Dg];
static __device__ float g_mean[256];
static __device__ float g_rstd[256];
static __device__ float g_mx3[Dg];
static __device__ float g_rx3[Dg];
static __device__ float g_psum[16*256];
static __device__ float g_psq[16*256];
static __device__ float g_msgsum[Ng*Dg];
static __device__ float g_S[Ng*Dg];
static __device__ float g_sbeta[Ng*Dg];
static __device__ float g_cnt[Ng];
static __device__ float g_mrelu[Ng*Dg];
static __device__ float g_gi[Ng*384];
static __device__ float g_gh[Ng*384];
static __device__ unsigned short g_Gh[DD*128];   // fp16 hi of alpha*W4
static __device__ unsigned short g_Gl[DD*128];   // fp16 (lo*4096)

// ---------- helpers (base-sm_100 legal) ----------
__device__ __forceinline__ uint32_t smem_u32(const void* p) {
    uint32_t a;
    asm("{ .reg .u64 t; cvta.to.shared.u64 t, %1; cvt.u32.u64 %0, t; }" : "=r"(a) : "l"(p));
    return a;
}
__device__ __forceinline__ void mma_bf16(float* d, const uint32_t* a, const uint32_t* b, const float* c) {
    asm volatile("mma.sync.aligned.m16n8k16.row.col.f32.bf16.bf16.f32 "
        "{%0,%1,%2,%3}, {%4,%5,%6,%7}, {%8,%9}, {%10,%11,%12,%13};"
        : "=f"(d[0]),"=f"(d[1]),"=f"(d[2]),"=f"(d[3])
        : "r"(a[0]),"r"(a[1]),"r"(a[2]),"r"(a[3]), "r"(b[0]),"r"(b[1]),
          "f"(c[0]),"f"(c[1]),"f"(c[2]),"f"(c[3]));
}
__device__ __forceinline__ void mma_f16(float* d, const uint32_t* a, const uint32_t* b, const float* c) {
    asm volatile("mma.sync.aligned.m16n8k16.row.col.f32.f16.f16.f32 "
        "{%0,%1,%2,%3}, {%4,%5,%6,%7}, {%8,%9}, {%10,%11,%12,%13};"
        : "=f"(d[0]),"=f"(d[1]),"=f"(d[2]),"=f"(d[3])
        : "r"(a[0]),"r"(a[1]),"r"(a[2]),"r"(a[3]), "r"(b[0]),"r"(b[1]),
          "f"(c[0]),"f"(c[1]),"f"(c[2]),"f"(c[3]));
}
__device__ __forceinline__ void ldsm4(uint32_t* r, uint32_t addr) {
    asm volatile("ldmatrix.sync.aligned.m8n8.x4.shared.b16 {%0,%1,%2,%3}, [%4];"
        : "=r"(r[0]),"=r"(r[1]),"=r"(r[2]),"=r"(r[3]) : "r"(addr));
}
__device__ __forceinline__ void cp16(uint32_t dst, const void* src) {
    asm volatile("cp.async.cg.shared.global [%0], [%1], 16;" :: "r"(dst), "l"(src));
}
#define CP_COMMIT() asm volatile("cp.async.commit_group;" ::: "memory")
__device__ __forceinline__ uint32_t f2h2(float2 p) {
    __half2 h = __float22half2_rn(p);
    return *(uint32_t*)&h;
}

// ---------- tensor-core side GEMM: C[M,N]=A[M,K]@B[N,K]^T (+bias), fp32 I/O ----------
// bf16 3-product split: error ~1.5e-5. M%128==0, N%128==0, K%16==0.
#define HS 20   // SMEM row stride in floats (80B, 16B aligned)
#define HTILE (128*HS)
#define HGEMM_SMEM (4*HTILE*4)   // sA[2] + sB[2] fp32 tiles = 81920 B

__global__ __launch_bounds__(256) void hgemm_tn(
    const float* __restrict__ A, const float* __restrict__ B,
    float* __restrict__ C, const float* __restrict__ bias, int M, int Nc, int K)
{
    extern __shared__ float hsm[];
    float* sA = hsm;              // [2][128][HS]
    float* sB = hsm + 2*HTILE;    // [2][128][HS]
    uint32_t sAb = smem_u32(sA), sBb = smem_u32(sB);
    int tid = threadIdx.x, l = tid&31, wid = tid>>5;
    int m0 = blockIdx.y*128, n0 = blockIdx.x*128;
    int wm = (wid>>1)*32, wn = (wid&1)*64;
    int r = l>>2, c2 = (l&3)*2;

    float acc[2][8][4];
    #pragma unroll
    for (int mf=0;mf<2;++mf)
        #pragma unroll
        for (int nf=0;nf<8;++nf) { acc[mf][nf][0]=0;acc[mf][nf][1]=0;acc[mf][nf][2]=0;acc[mf][nf][3]=0; }

    int steps = K>>4;
    // prefetch step 0
    #pragma unroll
    for (int i=0;i<2;++i) {
        int q = tid + i*256, row = q>>2, c4 = q&3;
        cp16(sAb + (row*HS)*4 + c4*16, A + (size_t)(m0+row)*K + c4*4);
        cp16(sBb + (row*HS)*4 + c4*16, B + (size_t)(n0+row)*K + c4*4);
    }
    CP_COMMIT();

    for (int s=0; s<steps; ++s) {
        if (s+1 < steps) {
            int buf = (s+1)&1, k0 = (s+1)*16;
            #pragma unroll
            for (int i=0;i<2;++i) {
                int q = tid + i*256, row = q>>2, c4 = q&3;
                cp16(sAb + (buf*HTILE + row*HS)*4 + c4*16, A + (size_t)(m0+row)*K + k0 + c4*4);
                cp16(sBb + (buf*HTILE + row*HS)*4 + c4*16, B + (size_t)(n0+row)*K + k0 + c4*4);
            }
            CP_COMMIT();
            asm volatile("cp.async.wait_group 1;" ::: "memory");
        } else {
            asm volatile("cp.async.wait_group 0;" ::: "memory");
        }
        __syncthreads();

        const float* a_ = sA + (s&1)*HTILE;
        const float* b_ = sB + (s&1)*HTILE;
        uint32_t Ah[2][4], Al[2][4], Bh[8][2], Bl[8][2];
        #pragma unroll
        for (int mf=0;mf<2;++mf) {
            const float* r0 = a_ + (wm+mf*16+r)*HS;
            const float* r1 = a_ + (wm+mf*16+r+8)*HS;
            float2 p[4];
            p[0]=*(const float2*)&r0[c2];   p[1]=*(const float2*)&r1[c2];
            p[2]=*(const float2*)&r0[c2+8]; p[3]=*(const float2*)&r1[c2+8];
            #pragma unroll
            for (int q=0;q<4;++q) {
                uint32_t u0=__float_as_uint(p[q].x), u1=__float_as_uint(p[q].y);
                Ah[mf][q]=__byte_perm(u0,u1,0x7632);
                float h0=__uint_as_float(u0&0xFFFF0000u), h1=__uint_as_float(u1&0xFFFF0000u);
                __nv_bfloat162 lo=__floats2bfloat162_rn(p[q].x-h0,p[q].y-h1);
                Al[mf][q]=*(uint32_t*)&lo;
            }
        }
        #pragma unroll
        for (int nf=0;nf<8;++nf) {
            const float* rb = b_ + (wn+nf*8+r)*HS;
            float2 p0=*(const float2*)&rb[c2], p1=*(const float2*)&rb[c2+8];
            uint32_t u0=__float_as_uint(p0.x), u1=__float_as_uint(p0.y);
            Bh[nf][0]=__byte_perm(u0,u1,0x7632);
            float h0=__uint_as_float(u0&0xFFFF0000u), h1=__uint_as_float(u1&0xFFFF0000u);
            __nv_bfloat162 lo=__floats2bfloat162_rn(p0.x-h0,p0.y-h1);
            Bl[nf][0]=*(uint32_t*)&lo;
            u0=__float_as_uint(p1.x); u1=__float_as_uint(p1.y);
            Bh[nf][1]=__byte_perm(u0,u1,0x7632);
            h0=__uint_as_float(u0&0xFFFF0000u); h1=__uint_as_float(u1&0xFFFF0000u);
            lo=__floats2bfloat162_rn(p1.x-h0,p1.y-h1);
            Bl[nf][1]=*(uint32_t*)&lo;
        }
        __syncthreads();   // readers done before next prefetch overwrites

        #pragma unroll
        for (int mf=0;mf<2;++mf)
            #pragma unroll
            for (int nf=0;nf<8;++nf) {
                mma_bf16(acc[mf][nf], Ah[mf], Bh[nf], acc[mf][nf]);
                mma_bf16(acc[mf][nf], Ah[mf], Bl[nf], acc[mf][nf]);
                mma_bf16(acc[mf][nf], Al[mf], Bh[nf], acc[mf][nf]);
            }
    }
    #pragma unroll
    for (int mf=0;mf<2;++mf) {
        int row0 = m0+wm+mf*16+r;
        #pragma unroll
        for (int nf=0;nf<8;++nf) {
            int col = n0+wn+nf*8+c2;
            float2 o0 = make_float2(acc[mf][nf][0], acc[mf][nf][1]);
            float2 o1 = make_float2(acc[mf][nf][2], acc[mf][nf][3]);
            if (bias) {
                float2 bv = *(const float2*)&bias[col];
                o0.x+=bv.x; o0.y+=bv.y; o1.x+=bv.x; o1.y+=bv.y;
            }
            *(float2*)&C[(size_t)row0*Nc + col]     = o0;
            *(float2*)&C[(size_t)(row0+8)*Nc + col] = o1;
        }
    }
}

__global__ __launch_bounds__(256) void colstats_partial(
    const float* __restrict__ Z, int M, int C, float* __restrict__ psum, float* __restrict__ psq)
{
    int lane = threadIdx.x & 31, w = threadIdx.x >> 5;
    int c = blockIdx.x*32 + lane;
    int rows = M/gridDim.y, r0 = blockIdx.y*rows;
    float s=0.f, q=0.f;
    for (int r=r0+w; r<r0+rows; r+=8) { float v=Z[(size_t)r*C+c]; s+=v; q+=v*v; }
    __shared__ float ss[8][32], sq2[8][32];
    ss[w][lane]=s; sq2[w][lane]=q;
    __syncthreads();
    if (w==0) {
        #pragma unroll
        for (int i=1;i<8;++i){ s+=ss[i][lane]; q+=sq2[i][lane]; }
        psum[blockIdx.y*C+c]=s; psq[blockIdx.y*C+c]=q;
    }
}
__global__ void colstats_final(int M, int C, int splits,
    const float* __restrict__ psum, const float* __restrict__ psq,
    float* __restrict__ mean, float* __restrict__ rstd)
{
    int c = blockIdx.x*blockDim.x + threadIdx.x;
    if (c >= C) return;
    float s=0.f,q=0.f;
    for (int i=0;i<splits;++i){ s+=psum[i*C+c]; q+=psq[i*C+c]; }
    float m = s/(float)M;
    mean[c]=m; rstd[c]=rsqrtf(q/(float)M - m*m + 1e-5f);
}
__global__ void bnrelu_kernel(float* __restrict__ Z,
    const float* __restrict__ mean, const float* __restrict__ rstd,
    const float* __restrict__ g, const float* __restrict__ b, int total, int cmask)
{
    int i = blockIdx.x*256 + threadIdx.x;
    if (i >= total) return;
    int c = i & cmask;
    Z[i] = fmaxf((Z[i]-mean[c])*rstd[c]*g[c] + b[c], 0.f);
}
__global__ __launch_bounds__(256) void syrk_x3()
{
    __shared__ float sAcc[8][1024];
    int tid = threadIdx.x, lane = tid&31, w = tid>>5;
    int i0 = blockIdx.x*8;
    int seg = Eg/gridDim.y, e0 = blockIdx.y*seg, e1 = e0+seg;
    float acc[8][4];
    #pragma unroll
    for (int a=0;a<8;++a){acc[a][0]=0;acc[a][1]=0;acc[a][2]=0;acc[a][3]=0;}
    for (int e=e0+w; e<e1; e+=8) {
        const float* row = g_x3 + (size_t)e*128;
        float4 xj = *(const float4*)&row[lane*4];
        float4 x0 = *(const float4*)&row[i0];
        float4 x1 = *(const float4*)&row[i0+4];
        float xi[8]={x0.x,x0.y,x0.z,x0.w,x1.x,x1.y,x1.z,x1.w};
        float xv[4]={xj.x,xj.y,xj.z,xj.w};
        #pragma unroll
        for (int a=0;a<8;++a)
            #pragma unroll
            for (int b=0;b<4;++b) acc[a][b]+=xi[a]*xv[b];
    }
    #pragma unroll
    for (int a=0;a<8;++a)
        *(float4*)&sAcc[w][a*128+lane*4]=make_float4(acc[a][0],acc[a][1],acc[a][2],acc[a][3]);
    __syncthreads();
    for (int o=tid;o<1024;o+=256) {
        float s=0.f;
        #pragma unroll
        for (int ww=0;ww<8;++ww) s+=sAcc[ww][o];
        atomicAdd(&g_C3[(i0+(o>>7))*128 + (o&127)], s);
    }
}
__global__ void alphabeta_kernel(const float* __restrict__ W4,
    const float* __restrict__ g4, const float* __restrict__ b4)
{
    int c = blockIdx.x*blockDim.x + threadIdx.x;
    const float4* w = (const float4*)(W4 + (size_t)c*128);
    const float4* u = (const float4*)(g_U + (size_t)c*128);
    const float4* mx = (const float4*)g_mx3;
    float m4=0.f, q=0.f;
    #pragma unroll 8
    for (int i=0;i<32;++i) {
        float4 wv=w[i], uv=u[i], mv=mx[i];
        m4 += wv.x*mv.x + wv.y*mv.y + wv.z*mv.z + wv.w*mv.w;
        q  += wv.x*uv.x + wv.y*uv.y + wv.z*uv.z + wv.w*uv.w;
    }
    float var = q*(1.0f/(float)Eg) - m4*m4;
    float a = g4[c]*rsqrtf(var + 1e-5f);
    g_alpha[c]=a;
    g_betaT[(c&127)*128 + (c>>7)] = b4[c]-m4*a;   // betaT[k][d]
}
// split G = alpha*W4 into fp16 hi + fp16(lo*4096)
__global__ void gsplit_kernel(const float* __restrict__ W4)
{
    int idx = blockIdx.x*256 + threadIdx.x;   // < DD*128
    int c = idx >> 7;
    float v = g_alpha[c] * W4[idx];
    __half h = __float2half_rn(v);
    g_Gh[idx] = *(unsigned short*)&h;
    __half hl = __float2half_rn((v - __half2float(h)) * 4096.f);
    g_Gl[idx] = *(unsigned short*)&hl;
}
__global__ void zero_kernel()
{
    int i = blockIdx.x*256 + threadIdx.x;
    if (i < Ng*Dg) { g_msgsum[i]=0.f; g_S[i]=0.f; }
    if (i < Ng)    g_cnt[i]=0.f;
    if (i < Dg*Dg) g_C3[i]=0.f;
}
__global__ void cnt_kernel(const int* __restrict__ ei)
{
    int e = blockIdx.x*256 + threadIdx.x;
    if (e < Eg) atomicAdd(&g_cnt[ei[2*e+1]], 1.0f);
}
__global__ void ssum_kernel(const int* __restrict__ ei, const float* __restrict__ node)
{
    int idx = blockIdx.x*256 + threadIdx.x;
    if (idx >= Eg*128) return;
    int e = idx>>7, k = idx&127;
    atomicAdd(&g_S[(size_t)ei[2*e+1]*128 + k], node[(size_t)ei[2*e]*128 + k]);
}

// ---------- big fused GEMM: V'_d = x3_tile @ G_d^T, msg += xi[:,d] * V'_d ----------
#define ROWB   272
#define BUF_SPLIT (128*ROWB)
#define BUF_SIZE  (2*BUF_SPLIT)
#define XIT_OFF   (2*BUF_SIZE)
#define BIG_SMEM  (XIT_OFF + 65536)

__device__ __forceinline__ void load_G(int d, int tid, uint32_t smem_base) {
    const char* GH = (const char*)g_Gh;
    const char* GL = (const char*)g_Gl;
    uint32_t bufb = smem_base + (d&1)*BUF_SIZE;
    #pragma unroll
    for (int i=0;i<16;++i) {
        int q = tid + i*256;
        int split = q>>11, row = (q>>4)&127, c16 = q&15;
        const char* src = (split? GL : GH) + ((size_t)d*128 + row)*256 + c16*16;
        uint32_t dst = bufb + split*BUF_SPLIT + row*ROWB + c16*16;
        cp16(dst, src);
    }
    CP_COMMIT();
}

__global__ __launch_bounds__(256,1) void big_msg_kernel(
    const float* __restrict__ node, const int* __restrict__ ei)
{
    extern __shared__ char sm[];
    float* xiT = (float*)(sm + XIT_OFF);   // [128 d][128 e]
    __shared__ int sDst[128];
    int tid = threadIdx.x, l = tid&31, w = tid>>5;
    int e0 = blockIdx.x*128;

    {
        int e = tid>>1, hf = tid&1;
        int src = ei[2*(e0+e)];
        if (hf==0) sDst[e] = ei[2*(e0+e)+1];
        const float* nr = node + (size_t)src*128 + hf*64;
        #pragma unroll
        for (int i=0;i<16;++i) {
            float4 v = *(const float4*)&nr[i*4];
            int d = hf*64 + i*4;
            xiT[(d+0)*128+e]=v.x; xiT[(d+1)*128+e]=v.y; xiT[(d+2)*128+e]=v.z; xiT[(d+3)*128+e]=v.w;
        }
    }
    float* sx3 = (float*)sm;   // [128 e][128 j] (temp)
    {
        const float* xr = g_x3 + (size_t)e0*128;
        #pragma unroll
        for (int i=0;i<16;++i) {
            int u = tid + i*256;
            *(float4*)&sx3[u*4] = *(const float4*)&xr[u*4];
        }
    }
    __syncthreads();

    // register-resident fp16 A fragments (single precision split on B only)
    int ew = w*16;
    int r = l>>2, cq = (l&3)*2;
    uint32_t Af[8][4];
    {
        const float* Xr0 = sx3 + (size_t)(ew + r)*128;
        const float* Xr1 = sx3 + (size_t)(ew + r + 8)*128;
        #pragma unroll
        for (int jt=0;jt<8;++jt) {
            int c0 = jt*16 + cq;
            Af[jt][0] = f2h2(*(const float2*)&Xr0[c0]);
            Af[jt][1] = f2h2(*(const float2*)&Xr1[c0]);
            Af[jt][2] = f2h2(*(const float2*)&Xr0[c0+8]);
            Af[jt][3] = f2h2(*(const float2*)&Xr1[c0+8]);
        }
    }
    __syncthreads();   // sx3 dead; buffers free

    uint32_t smem_base = smem_u32(sm);
    int ln = ((l>>4)&1)*8 + (l&7);
    int colsel = (l>>3)&1;
    uint32_t laneoff = (uint32_t)ln*ROWB + colsel*16;

    float msg[16][4];
    #pragma unroll
    for (int nt=0;nt<16;++nt) { msg[nt][0]=0;msg[nt][1]=0;msg[nt][2]=0;msg[nt][3]=0; }

    load_G(0, tid, smem_base);
    const float LS = 2.44140625e-4f;   // 1/4096

    for (int d = 0; d < 128; ++d) {
        if (d < 127) {
            load_G(d+1, tid, smem_base);
            asm volatile("cp.async.wait_group 1;" ::: "memory");
        } else {
            asm volatile("cp.async.wait_group 0;" ::: "memory");
        }
        __syncthreads();

        uint32_t bufb = smem_base + (d&1)*BUF_SIZE;
        uint32_t aH = bufb + laneoff;
        uint32_t aL = bufb + BUF_SPLIT + laneoff;
        float xi0 = xiT[d*128 + ew + r];
        float xi1 = xiT[d*128 + ew + r + 8];

        #pragma unroll
        for (int ntp = 0; ntp < 8; ++ntp) {
            float vh[8] = {0,0,0,0,0,0,0,0};
            float vl[8] = {0,0,0,0,0,0,0,0};
            uint32_t rowoff = (uint32_t)ntp*16*ROWB;
            #pragma unroll
            for (int jt = 0; jt < 8; ++jt) {
                uint32_t bh[4], bl[4];
                ldsm4(bh, aH + rowoff + jt*32);
                ldsm4(bl, aL + rowoff + jt*32);
                mma_f16(vh,   Af[jt], bh,   vh);
                mma_f16(vh+4, Af[jt], bh+2, vh+4);
                mma_f16(vl,   Af[jt], bl,   vl);
                mma_f16(vl+4, Af[jt], bl+2, vl+4);
            }
            msg[2*ntp  ][0] += xi0*(vh[0] + LS*vl[0]);
            msg[2*ntp  ][1] += xi0*(vh[1] + LS*vl[1]);
            msg[2*ntp  ][2] += xi1*(vh[2] + LS*vl[2]);
            msg[2*ntp  ][3] += xi1*(vh[3] + LS*vl[3]);
            msg[2*ntp+1][0] += xi0*(vh[4] + LS*vl[4]);
            msg[2*ntp+1][1] += xi0*(vh[5] + LS*vl[5]);
            msg[2*ntp+1][2] += xi1*(vh[6] + LS*vl[6]);
            msg[2*ntp+1][3] += xi1*(vh[7] + LS*vl[7]);
        }
        __syncthreads();
    }

    int d0 = sDst[ew + r], d1 = sDst[ew + r + 8];
    #pragma unroll
    for (int nt = 0; nt < 16; ++nt) {
        int k = nt*8 + cq;
        atomicAdd(&g_msgsum[(size_t)d0*128 + k],     msg[nt][0]);
        atomicAdd(&g_msgsum[(size_t)d0*128 + k + 1], msg[nt][1]);
        atomicAdd(&g_msgsum[(size_t)d1*128 + k],     msg[nt][2]);
        atomicAdd(&g_msgsum[(size_t)d1*128 + k + 1], msg[nt][3]);
    }
}

__global__ void finalize_msg(const float* __restrict__ bias)
{
    int i = blockIdx.x*256 + threadIdx.x;
    if (i >= Ng*Dg) return;
    float c = fmaxf(g_cnt[i>>7], 1.0f);
    g_mrelu[i] = fmaxf((g_msgsum[i] + g_sbeta[i])/c + bias[i&127], 0.0f);
}
__global__ void gru_kernel(const float* __restrict__ h0, float* __restrict__ out, int twice)
{
    int i = blockIdx.x*256 + threadIdx.x;
    if (i >= Ng*Dg) return;
    int n = i>>7, k = i&127;
    const float* gir = g_gi + (size_t)n*384;
    const float* ghr = g_gh + (size_t)n*384;
    float r = 1.f/(1.f + expf(-(gir[k]     + ghr[k])));
    float z = 1.f/(1.f + expf(-(gir[128+k] + ghr[128+k])));
    float nn = tanhf(gir[256+k] + r*ghr[256+k]);
    float hn = (1.f - z)*nn + z*h0[i];
    out[i] = hn;
    if (twice) out[Ng*Dg + i] = hn;
}

static float* sym(const void* s) { void* p=0; cudaGetSymbolAddress(&p, s); return (float*)p; }

extern "C" void kernel_launch(void* const* d_in, const int* in_sizes, int n_in,
                              void* d_out, int out_size)
{
    const float* node   = (const float*)d_in[0];
    const int*   ei     = (const int*)  d_in[1];
    const float* edge   = (const float*)d_in[2];
    const float* hidden = (const float*)d_in[3];
    const float* W1=(const float*)d_in[4],  *g1=(const float*)d_in[5],  *b1=(const float*)d_in[6];
    const float* W2=(const float*)d_in[7],  *g2=(const float*)d_in[8],  *b2=(const float*)d_in[9];
    const float* W3=(const float*)d_in[10], *g3=(const float*)d_in[11], *b3=(const float*)d_in[12];
    const float* W4=(const float*)d_in[13];
    const float* g4=(const float*)d_in[14], *b4=(const float*)d_in[15];
    const float* bias=(const float*)d_in[16];
    const float* W_ih=(const float*)d_in[17], *W_hh=(const float*)d_in[18];
    const float* b_ih=(const float*)d_in[19], *b_hh=(const float*)d_in[20];
    (void)in_sizes; (void)n_in;

    float *x1=sym(g_x1), *x2=sym(g_x2), *x3=sym(g_x3);
    float *U=sym(g_U), *C3=sym(g_C3);
    float *mn=sym(g_mean), *rs=sym(g_rstd);
    float *ps=sym(g_psum), *pq=sym(g_psq);
    float *mx3=sym(g_mx3), *rx3=sym(g_rx3);
    float *mr=sym(g_mrelu), *gi=sym(g_gi), *gh=sym(g_gh);
    float *S=sym(g_S), *bT=sym(g_betaT), *sb=sym(g_sbeta);

    cudaFuncSetAttribute(hgemm_tn, cudaFuncAttributeMaxDynamicSharedMemorySize, HGEMM_SMEM);
    cudaFuncSetAttribute(big_msg_kernel, cudaFuncAttributeMaxDynamicSharedMemorySize, BIG_SMEM);

    zero_kernel<<<2048,256>>>();

    hgemm_tn<<<dim3(2,128),256,HGEMM_SMEM>>>(edge, W1, x1, nullptr, Eg, 256, 16);
    colstats_partial<<<dim3(8,16),256>>>(x1, Eg, 256, ps, pq);
    colstats_final<<<1,256>>>(Eg, 256, 16, ps, pq, mn, rs);
    bnrelu_kernel<<<Eg,256>>>(x1, mn, rs, g1, b1, Eg*256, 255);

    hgemm_tn<<<dim3(2,128),256,HGEMM_SMEM>>>(x1, W2, x2, nullptr, Eg, 256, 256);
    colstats_partial<<<dim3(8,16),256>>>(x2, Eg, 256, ps, pq);
    colstats_final<<<1,256>>>(Eg, 256, 16, ps, pq, mn, rs);
    bnrelu_kernel<<<Eg,256>>>(x2, mn, rs, g2, b2, Eg*256, 255);

    hgemm_tn<<<dim3(1,128),256,HGEMM_SMEM>>>(x2, W3, x3, nullptr, Eg, 128, 256);
    colstats_partial<<<dim3(4,16),256>>>(x3, Eg, 128, ps, pq);
    colstats_final<<<1,128>>>(Eg, 128, 16, ps, pq, mn, rs);
    bnrelu_kernel<<<Eg/2,256>>>(x3, mn, rs, g3, b3, Eg*128, 127);

    colstats_partial<<<dim3(4,16),256>>>(x3, Eg, 128, ps, pq);
    colstats_final<<<1,128>>>(Eg, 128, 16, ps, pq, mx3, rx3);
    syrk_x3<<<dim3(16,32),256>>>();
    hgemm_tn<<<dim3(1,128),256,HGEMM_SMEM>>>(W4, C3, U, nullptr, DD, 128, 128);
    alphabeta_kernel<<<64,256>>>(W4, g4, b4);
    gsplit_kernel<<<DD*128/256,256>>>(W4);

    cnt_kernel<<<64,256>>>(ei);
    ssum_kernel<<<Eg*128/256,256>>>(ei, node);

    big_msg_kernel<<<128,256,BIG_SMEM>>>(node, ei);

    hgemm_tn<<<dim3(1,32),256,HGEMM_SMEM>>>(S, bT, sb, nullptr, Ng, 128, 128);
    finalize_msg<<<2048,256>>>(bias);

    hgemm_tn<<<dim3(3,32),256,HGEMM_SMEM>>>(mr,     W_ih, gi, b_ih, Ng, 384, 128);
    hgemm_tn<<<dim3(3,32),256,HGEMM_SMEM>>>(hidden, W_hh, gh, b_hh, Ng, 384, 128);

    int twice = (out_size >= 2*Ng*Dg) ? 1 : 0;
    gru_kernel<<<2048,256>>>(hidden, (float*)d_out, twice);
}

// round 7
// speedup vs baseline: 3.6482x; 1.1716x over previous
#include <cuda_runtime.h>
#include <cuda_bf16.h>
#include <cuda_fp16.h>
#include <cstdint>

#define Eg 16384
#define Ng 4096
#define Dg 128
#define DD 16384

static __device__ float g_x1[Eg*256];
static __device__ float g_x2[Eg*256];
static __device__ float g_x3[Eg*Dg];
static __device__ float g_U[DD*Dg];
static __device__ float g_C3[Dg*Dg];
static __device__ float g_alpha[DD];
static __device__ float g_ps1[256], g_pq1[256];
static __device__ float g_ps2[256], g_pq2[256];
static __device__ float g_ps3[128], g_pq3[128];
static __device__ float g_mx3sum[128];
static __device__ float g_msgsum[Ng*Dg];
static __device__ float g_S[Ng*Dg];
static __device__ float g_cnt[Ng];
static __device__ float g_mrelu[Ng*Dg];
static __device__ float g_gi[Ng*384];
static __device__ float g_gh[Ng*384];
static __device__ unsigned short g_Gh[DD*128];
static __device__ unsigned short g_Gl[DD*128];
// presplit weights (bf16 hi/lo)
static __device__ unsigned short g_W1h[4096],   g_W1l[4096];
static __device__ unsigned short g_W2h[65536],  g_W2l[65536];
static __device__ unsigned short g_W3h[32768],  g_W3l[32768];
static __device__ unsigned short g_Wihh[49152], g_Wihl[49152];
static __device__ unsigned short g_Whhh[49152], g_Whhl[49152];
static __device__ unsigned short g_C3h[16384],  g_C3l[16384];
static __device__ unsigned short g_bTh[16384],  g_bTl[16384];

// ---------- helpers ----------
__device__ __forceinline__ uint32_t smem_u32(const void* p) {
    uint32_t a;
    asm("{ .reg .u64 t; cvta.to.shared.u64 t, %1; cvt.u32.u64 %0, t; }" : "=r"(a) : "l"(p));
    return a;
}
__device__ __forceinline__ void mma_bf16(float* d, const uint32_t* a, const uint32_t* b, const float* c) {
    asm volatile("mma.sync.aligned.m16n8k16.row.col.f32.bf16.bf16.f32 "
        "{%0,%1,%2,%3}, {%4,%5,%6,%7}, {%8,%9}, {%10,%11,%12,%13};"
        : "=f"(d[0]),"=f"(d[1]),"=f"(d[2]),"=f"(d[3])
        : "r"(a[0]),"r"(a[1]),"r"(a[2]),"r"(a[3]), "r"(b[0]),"r"(b[1]),
          "f"(c[0]),"f"(c[1]),"f"(c[2]),"f"(c[3]));
}
__device__ __forceinline__ void mma_f16(float* d, const uint32_t* a, const uint32_t* b, const float* c) {
    asm volatile("mma.sync.aligned.m16n8k16.row.col.f32.f16.f16.f32 "
        "{%0,%1,%2,%3}, {%4,%5,%6,%7}, {%8,%9}, {%10,%11,%12,%13};"
        : "=f"(d[0]),"=f"(d[1]),"=f"(d[2]),"=f"(d[3])
        : "r"(a[0]),"r"(a[1]),"r"(a[2]),"r"(a[3]), "r"(b[0]),"r"(b[1]),
          "f"(c[0]),"f"(c[1]),"f"(c[2]),"f"(c[3]));
}
__device__ __forceinline__ void ldsm4(uint32_t* r, uint32_t addr) {
    asm volatile("ldmatrix.sync.aligned.m8n8.x4.shared.b16 {%0,%1,%2,%3}, [%4];"
        : "=r"(r[0]),"=r"(r[1]),"=r"(r[2]),"=r"(r[3]) : "r"(addr));
}
__device__ __forceinline__ void cp16(uint32_t dst, const void* src) {
    asm volatile("cp.async.cg.shared.global [%0], [%1], 16;" :: "r"(dst), "l"(src));
}
#define CP_COMMIT() asm volatile("cp.async.commit_group;" ::: "memory")
__device__ __forceinline__ uint32_t f2h2(float2 p) {
    __half2 h = __float22half2_rn(p);
    return *(uint32_t*)&h;
}
__device__ __forceinline__ void split2(float2 p, uint32_t& hi, uint32_t& lo) {
    uint32_t u0=__float_as_uint(p.x), u1=__float_as_uint(p.y);
    hi = __byte_perm(u0,u1,0x7632);
    float h0=__uint_as_float(u0&0xFFFF0000u), h1=__uint_as_float(u1&0xFFFF0000u);
    __nv_bfloat162 l2=__floats2bfloat162_rn(p.x-h0,p.y-h1);
    lo = *(uint32_t*)&l2;
}

// ---------- weight presplit ----------
__global__ void wsplit_kernel(const float* W1, const float* W2, const float* W3,
                              const float* Wih, const float* Whh)
{
    int i = blockIdx.x*256 + threadIdx.x;   // < 200704
    const float* src; unsigned short *dh, *dl; int off;
    if (i < 4096)        { src=W1;  dh=g_W1h;  dl=g_W1l;  off=i; }
    else if (i < 69632)  { src=W2;  dh=g_W2h;  dl=g_W2l;  off=i-4096; }
    else if (i < 102400) { src=W3;  dh=g_W3h;  dl=g_W3l;  off=i-69632; }
    else if (i < 151552) { src=Wih; dh=g_Wihh; dl=g_Wihl; off=i-102400; }
    else                 { src=Whh; dh=g_Whhh; dl=g_Whhl; off=i-151552; }
    float v = src[off];
    uint32_t u = __float_as_uint(v);
    dh[off] = (unsigned short)(u>>16);
    __nv_bfloat16 lb = __float2bfloat16_rn(v - __uint_as_float(u & 0xFFFF0000u));
    dl[off] = *(unsigned short*)&lb;
}
__global__ void csplit_kernel()
{
    int i = blockIdx.x*256 + threadIdx.x;   // < 16384
    float v = g_C3[i];
    uint32_t u = __float_as_uint(v);
    g_C3h[i] = (unsigned short)(u>>16);
    __nv_bfloat16 lb = __float2bfloat16_rn(v - __uint_as_float(u & 0xFFFF0000u));
    g_C3l[i] = *(unsigned short*)&lb;
}

// ---------- unified tensor-core GEMM ----------
// C[M,N] = A[M,K] @ B[N,K]^T; B presplit bf16 hi/lo; 3-product (AhBh+AlBh+AhBl).
// amode 0: A raw; 1: A <- relu((A-mean)*rstd*g+b) with stats from psA/pqA (invE divisor).
// emode 0: store (+bias); 1: store + atomic col stats into psO/pqO;
//       2: store relu((acc+msgsum)/max(cnt,1)+bias) into C (msg finalize).
#define SA_OFF(s)  ((s)*10240)
#define SBH_OFF(s) (20480 + (s)*12288)
#define SBL_OFF(s) (20480 + (s)*12288 + 6144)
#define SSC_OFF    45056
#define SSH_OFF    46080
#define H_SMEM     47104

__global__ __launch_bounds__(256) void hgemm(
    const float* __restrict__ A,
    const unsigned short* __restrict__ Bh, const unsigned short* __restrict__ Bl,
    float* __restrict__ C, const float* __restrict__ bias,
    int M, int Nc, int K,
    int amode, const float* __restrict__ psA, const float* __restrict__ pqA,
    const float* __restrict__ gA, const float* __restrict__ bA, float invE,
    int emode, float* __restrict__ psO, float* __restrict__ pqO)
{
    extern __shared__ char sm[];
    uint32_t smb = smem_u32(sm);
    float* sScale = (float*)(sm + SSC_OFF);
    float* sShift = (float*)(sm + SSH_OFF);
    int tid = threadIdx.x, l = tid&31, wid = tid>>5;
    int m0 = blockIdx.y*128, n0 = blockIdx.x*128;
    int wm = (wid>>1)*32, wn = (wid&1)*64;
    int r = l>>2, c2 = (l&3)*2;
    int ln = ((l>>4)&1)*8 + (l&7);
    int colsel = (l>>3)&1;

    if (amode) {
        for (int c = tid; c < K; c += 256) {
            float m = psA[c]*invE;
            float var = pqA[c]*invE - m*m;
            float sc = rsqrtf(var + 1e-5f) * gA[c];
            sScale[c] = sc;
            sShift[c] = bA[c] - m*sc;
        }
    }

    float acc[2][8][4];
    #pragma unroll
    for (int mf=0;mf<2;++mf)
        #pragma unroll
        for (int nf=0;nf<8;++nf) { acc[mf][nf][0]=0;acc[mf][nf][1]=0;acc[mf][nf][2]=0;acc[mf][nf][3]=0; }

    int steps = K>>4;
    // prefetch k-step 0
    {
        #pragma unroll
        for (int i=0;i<2;++i) {
            int q = tid + i*256, row = q>>2, c4 = q&3;
            cp16(smb + SA_OFF(0) + row*80 + c4*16, A + (size_t)(m0+row)*K + c4*4);
        }
        int row = tid>>1, c = tid&1;
        cp16(smb + SBH_OFF(0) + row*48 + c*16, Bh + (size_t)(n0+row)*K + c*8);
        cp16(smb + SBL_OFF(0) + row*48 + c*16, Bl + (size_t)(n0+row)*K + c*8);
        CP_COMMIT();
    }

    for (int s=0; s<steps; ++s) {
        if (s+1 < steps) {
            int b = (s+1)&1, k0 = (s+1)*16;
            #pragma unroll
            for (int i=0;i<2;++i) {
                int q = tid + i*256, row = q>>2, c4 = q&3;
                cp16(smb + SA_OFF(b) + row*80 + c4*16, A + (size_t)(m0+row)*K + k0 + c4*4);
            }
            int row = tid>>1, c = tid&1;
            cp16(smb + SBH_OFF(b) + row*48 + c*16, Bh + (size_t)(n0+row)*K + k0 + c*8);
            cp16(smb + SBL_OFF(b) + row*48 + c*16, Bl + (size_t)(n0+row)*K + k0 + c*8);
            CP_COMMIT();
            asm volatile("cp.async.wait_group 1;" ::: "memory");
        } else {
            asm volatile("cp.async.wait_group 0;" ::: "memory");
        }
        __syncthreads();

        const float* a_ = (const float*)(sm + SA_OFF(s&1));
        int k0 = s*16;
        uint32_t Ah[2][4], Al[2][4];
        #pragma unroll
        for (int mf=0;mf<2;++mf) {
            const float* r0 = a_ + (wm+mf*16+r)*20;
            const float* r1 = a_ + (wm+mf*16+r+8)*20;
            float2 p[4];
            p[0]=*(const float2*)&r0[c2];   p[1]=*(const float2*)&r1[c2];
            p[2]=*(const float2*)&r0[c2+8]; p[3]=*(const float2*)&r1[c2+8];
            if (amode) {
                float sc0=sScale[k0+c2], sc1=sScale[k0+c2+1];
                float sh0=sShift[k0+c2], sh1=sShift[k0+c2+1];
                float sc2=sScale[k0+c2+8], sc3=sScale[k0+c2+9];
                float sh2=sShift[k0+c2+8], sh3=sShift[k0+c2+9];
                p[0].x=fmaxf(p[0].x*sc0+sh0,0.f); p[0].y=fmaxf(p[0].y*sc1+sh1,0.f);
                p[1].x=fmaxf(p[1].x*sc0+sh0,0.f); p[1].y=fmaxf(p[1].y*sc1+sh1,0.f);
                p[2].x=fmaxf(p[2].x*sc2+sh2,0.f); p[2].y=fmaxf(p[2].y*sc3+sh3,0.f);
                p[3].x=fmaxf(p[3].x*sc2+sh2,0.f); p[3].y=fmaxf(p[3].y*sc3+sh3,0.f);
            }
            #pragma unroll
            for (int q=0;q<4;++q) split2(p[q], Ah[mf][q], Al[mf][q]);
        }
        uint32_t bh4[4][4], bl4[4][4];
        #pragma unroll
        for (int i=0;i<4;++i) {
            uint32_t boff = (uint32_t)(wn + 16*i + ln)*48 + colsel*16;
            ldsm4(bh4[i], smb + SBH_OFF(s&1) + boff);
            ldsm4(bl4[i], smb + SBL_OFF(s&1) + boff);
        }
        __syncthreads();

        #pragma unroll
        for (int mf=0;mf<2;++mf)
            #pragma unroll
            for (int nf=0;nf<8;++nf) {
                const uint32_t* bh = &bh4[nf>>1][(nf&1)*2];
                const uint32_t* bl = &bl4[nf>>1][(nf&1)*2];
                mma_bf16(acc[mf][nf], Ah[mf], bh, acc[mf][nf]);
                mma_bf16(acc[mf][nf], Al[mf], bh, acc[mf][nf]);
                mma_bf16(acc[mf][nf], Ah[mf], bl, acc[mf][nf]);
            }
    }

    if (emode == 2) {
        #pragma unroll
        for (int mf=0;mf<2;++mf) {
            int row0 = m0+wm+mf*16+r;
            float cn0 = fmaxf(g_cnt[row0],1.f), cn1 = fmaxf(g_cnt[row0+8],1.f);
            #pragma unroll
            for (int nf=0;nf<8;++nf) {
                int col = n0+wn+nf*8+c2;
                float2 bv = *(const float2*)&bias[col];
                float2 m0v = *(const float2*)&g_msgsum[(size_t)row0*Nc + col];
                float2 m1v = *(const float2*)&g_msgsum[(size_t)(row0+8)*Nc + col];
                float2 o0, o1;
                o0.x = fmaxf((acc[mf][nf][0]+m0v.x)/cn0 + bv.x, 0.f);
                o0.y = fmaxf((acc[mf][nf][1]+m0v.y)/cn0 + bv.y, 0.f);
                o1.x = fmaxf((acc[mf][nf][2]+m1v.x)/cn1 + bv.x, 0.f);
                o1.y = fmaxf((acc[mf][nf][3]+m1v.y)/cn1 + bv.y, 0.f);
                *(float2*)&C[(size_t)row0*Nc + col]     = o0;
                *(float2*)&C[(size_t)(row0+8)*Nc + col] = o1;
            }
        }
        return;
    }
    #pragma unroll
    for (int mf=0;mf<2;++mf) {
        int row0 = m0+wm+mf*16+r;
        #pragma unroll
        for (int nf=0;nf<8;++nf) {
            int col = n0+wn+nf*8+c2;
            float2 o0 = make_float2(acc[mf][nf][0], acc[mf][nf][1]);
            float2 o1 = make_float2(acc[mf][nf][2], acc[mf][nf][3]);
            if (bias) {
                float2 bv = *(const float2*)&bias[col];
                o0.x+=bv.x; o0.y+=bv.y; o1.x+=bv.x; o1.y+=bv.y;
            }
            *(float2*)&C[(size_t)row0*Nc + col]     = o0;
            *(float2*)&C[(size_t)(row0+8)*Nc + col] = o1;
        }
    }
    if (emode == 1) {
        #pragma unroll
        for (int nf=0;nf<8;++nf) {
            float s0=0,s1=0,q0=0,q1=0;
            #pragma unroll
            for (int mf=0;mf<2;++mf) {
                float a0=acc[mf][nf][0], a1=acc[mf][nf][1], a2=acc[mf][nf][2], a3=acc[mf][nf][3];
                s0+=a0+a2; s1+=a1+a3; q0+=a0*a0+a2*a2; q1+=a1*a1+a3*a3;
            }
            #pragma unroll
            for (int st=4; st<32; st<<=1) {
                s0 += __shfl_xor_sync(0xFFFFFFFF, s0, st);
                s1 += __shfl_xor_sync(0xFFFFFFFF, s1, st);
                q0 += __shfl_xor_sync(0xFFFFFFFF, q0, st);
                q1 += __shfl_xor_sync(0xFFFFFFFF, q1, st);
            }
            if (l < 4) {
                int col = n0+wn+nf*8+c2;
                atomicAdd(&psO[col], s0);   atomicAdd(&psO[col+1], s1);
                atomicAdd(&pqO[col], q0);   atomicAdd(&pqO[col+1], q1);
            }
        }
    }
}

// ---------- x3 BN+relu materialize + column sums ----------
__global__ __launch_bounds__(256) void bnx3_kernel(
    const float* __restrict__ g3, const float* __restrict__ b3)
{
    __shared__ float scol[256];
    int tid = threadIdx.x;
    int col = tid & 127, half = tid >> 7;
    float m = g_ps3[col]*(1.f/Eg);
    float var = g_pq3[col]*(1.f/Eg) - m*m;
    float sc = rsqrtf(var+1e-5f)*g3[col];
    float sh = b3[col] - m*sc;
    int r0 = blockIdx.x*128 + half;
    float s = 0.f;
    for (int i = 0; i < 64; ++i) {
        size_t idx = (size_t)(r0 + 2*i)*128 + col;
        float v = fmaxf(g_x3[idx]*sc + sh, 0.f);
        g_x3[idx] = v;
        s += v;
    }
    scol[tid] = s;
    __syncthreads();
    if (half == 0) atomicAdd(&g_mx3sum[col], scol[col] + scol[col+128]);
}

__global__ __launch_bounds__(256) void syrk_x3()
{
    __shared__ float sAcc[8][1024];
    int tid = threadIdx.x, lane = tid&31, w = tid>>5;
    int i0 = blockIdx.x*8;
    int seg = Eg/gridDim.y, e0 = blockIdx.y*seg, e1 = e0+seg;
    float acc[8][4];
    #pragma unroll
    for (int a=0;a<8;++a){acc[a][0]=0;acc[a][1]=0;acc[a][2]=0;acc[a][3]=0;}
    for (int e=e0+w; e<e1; e+=8) {
        const float* row = g_x3 + (size_t)e*128;
        float4 xj = *(const float4*)&row[lane*4];
        float4 x0 = *(const float4*)&row[i0];
        float4 x1 = *(const float4*)&row[i0+4];
        float xi[8]={x0.x,x0.y,x0.z,x0.w,x1.x,x1.y,x1.z,x1.w};
        float xv[4]={xj.x,xj.y,xj.z,xj.w};
        #pragma unroll
        for (int a=0;a<8;++a)
            #pragma unroll
            for (int b=0;b<4;++b) acc[a][b]+=xi[a]*xv[b];
    }
    #pragma unroll
    for (int a=0;a<8;++a)
        *(float4*)&sAcc[w][a*128+lane*4]=make_float4(acc[a][0],acc[a][1],acc[a][2],acc[a][3]);
    __syncthreads();
    for (int o=tid;o<1024;o+=256) {
        float s=0.f;
        #pragma unroll
        for (int ww=0;ww<8;++ww) s+=sAcc[ww][o];
        atomicAdd(&g_C3[(i0+(o>>7))*128 + (o&127)], s);
    }
}
__global__ void alphabeta_kernel(const float* __restrict__ W4,
    const float* __restrict__ g4, const float* __restrict__ b4)
{
    int c = blockIdx.x*blockDim.x + threadIdx.x;
    const float4* w = (const float4*)(W4 + (size_t)c*128);
    const float4* u = (const float4*)(g_U + (size_t)c*128);
    const float4* mx = (const float4*)g_mx3sum;
    float ms=0.f, q=0.f;
    #pragma unroll 8
    for (int i=0;i<32;++i) {
        float4 wv=w[i], uv=u[i], mv=mx[i];
        ms += wv.x*mv.x + wv.y*mv.y + wv.z*mv.z + wv.w*mv.w;
        q  += wv.x*uv.x + wv.y*uv.y + wv.z*uv.z + wv.w*uv.w;
    }
    float m4 = ms*(1.f/Eg);
    float var = q*(1.0f/(float)Eg) - m4*m4;
    float a = g4[c]*rsqrtf(var + 1e-5f);
    g_alpha[c]=a;
    float bv = b4[c]-m4*a;
    int t = (c&127)*128 + (c>>7);          // betaT[k][d]
    uint32_t uu = __float_as_uint(bv);
    g_bTh[t] = (unsigned short)(uu>>16);
    __nv_bfloat16 lb = __float2bfloat16_rn(bv - __uint_as_float(uu & 0xFFFF0000u));
    g_bTl[t] = *(unsigned short*)&lb;
}
__global__ void gsplit_kernel(const float* __restrict__ W4)
{
    int idx = blockIdx.x*256 + threadIdx.x;
    int c = idx >> 7;
    float v = g_alpha[c] * W4[idx];
    __half h = __float2half_rn(v);
    g_Gh[idx] = *(unsigned short*)&h;
    __half hl = __float2half_rn((v - __half2float(h)) * 4096.f);
    g_Gl[idx] = *(unsigned short*)&hl;
}
__global__ void zero_kernel()
{
    int i = blockIdx.x*256 + threadIdx.x;
    if (i < Ng*Dg) { g_msgsum[i]=0.f; g_S[i]=0.f; }
    if (i < Ng)    g_cnt[i]=0.f;
    if (i < Dg*Dg) g_C3[i]=0.f;
    if (i < 256)   { g_ps1[i]=0.f; g_pq1[i]=0.f; g_ps2[i]=0.f; g_pq2[i]=0.f; }
    if (i < 128)   { g_ps3[i]=0.f; g_pq3[i]=0.f; g_mx3sum[i]=0.f; }
}
__global__ void ssum_kernel(const int* __restrict__ ei, const float* __restrict__ node)
{
    int idx = blockIdx.x*256 + threadIdx.x;
    if (idx >= Eg*128) return;
    int e = idx>>7, k = idx&127;
    int dst = ei[2*e+1];
    atomicAdd(&g_S[(size_t)dst*128 + k], node[(size_t)ei[2*e]*128 + k]);
    if (k == 0) atomicAdd(&g_cnt[dst], 1.0f);
}

// ---------- big fused GEMM (unchanged from R6 pass) ----------
#define ROWB   272
#define BUF_SPLIT (128*ROWB)
#define BUF_SIZE  (2*BUF_SPLIT)
#define XIT_OFF   (2*BUF_SIZE)
#define BIG_SMEM  (XIT_OFF + 65536)

__device__ __forceinline__ void load_G(int d, int tid, uint32_t smem_base) {
    const char* GH = (const char*)g_Gh;
    const char* GL = (const char*)g_Gl;
    uint32_t bufb = smem_base + (d&1)*BUF_SIZE;
    #pragma unroll
    for (int i=0;i<16;++i) {
        int q = tid + i*256;
        int split = q>>11, row = (q>>4)&127, c16 = q&15;
        const char* src = (split? GL : GH) + ((size_t)d*128 + row)*256 + c16*16;
        uint32_t dst = bufb + split*BUF_SPLIT + row*ROWB + c16*16;
        cp16(dst, src);
    }
    CP_COMMIT();
}

__global__ __launch_bounds__(256,1) void big_msg_kernel(
    const float* __restrict__ node, const int* __restrict__ ei)
{
    extern __shared__ char sm[];
    float* xiT = (float*)(sm + XIT_OFF);
    __shared__ int sDst[128];
    int tid = threadIdx.x, l = tid&31, w = tid>>5;
    int e0 = blockIdx.x*128;
    {
        int e = tid>>1, hf = tid&1;
        int src = ei[2*(e0+e)];
        if (hf==0) sDst[e] = ei[2*(e0+e)+1];
        const float* nr = node + (size_t)src*128 + hf*64;
        #pragma unroll
        for (int i=0;i<16;++i) {
            float4 v = *(const float4*)&nr[i*4];
            int d = hf*64 + i*4;
            xiT[(d+0)*128+e]=v.x; xiT[(d+1)*128+e]=v.y; xiT[(d+2)*128+e]=v.z; xiT[(d+3)*128+e]=v.w;
        }
    }
    float* sx3 = (float*)sm;
    {
        const float* xr = g_x3 + (size_t)e0*128;
        #pragma unroll
        for (int i=0;i<16;++i) {
            int u = tid + i*256;
            *(float4*)&sx3[u*4] = *(const float4*)&xr[u*4];
        }
    }
    __syncthreads();
    int ew = w*16;
    int r = l>>2, cq = (l&3)*2;
    uint32_t Af[8][4];
    {
        const float* Xr0 = sx3 + (size_t)(ew + r)*128;
        const float* Xr1 = sx3 + (size_t)(ew + r + 8)*128;
        #pragma unroll
        for (int jt=0;jt<8;++jt) {
            int c0 = jt*16 + cq;
            Af[jt][0] = f2h2(*(const float2*)&Xr0[c0]);
            Af[jt][1] = f2h2(*(const float2*)&Xr1[c0]);
            Af[jt][2] = f2h2(*(const float2*)&Xr0[c0+8]);
            Af[jt][3] = f2h2(*(const float2*)&Xr1[c0+8]);
        }
    }
    __syncthreads();

    uint32_t smem_base = smem_u32(sm);
    int ln = ((l>>4)&1)*8 + (l&7);
    int colsel = (l>>3)&1;
    uint32_t laneoff = (uint32_t)ln*ROWB + colsel*16;

    float msg[16][4];
    #pragma unroll
    for (int nt=0;nt<16;++nt) { msg[nt][0]=0;msg[nt][1]=0;msg[nt][2]=0;msg[nt][3]=0; }

    load_G(0, tid, smem_base);
    const float LS = 2.44140625e-4f;

    for (int d = 0; d < 128; ++d) {
        if (d < 127) {
            load_G(d+1, tid, smem_base);
            asm volatile("cp.async.wait_group 1;" ::: "memory");
        } else {
            asm volatile("cp.async.wait_group 0;" ::: "memory");
        }
        __syncthreads();

        uint32_t bufb = smem_base + (d&1)*BUF_SIZE;
        uint32_t aH = bufb + laneoff;
        uint32_t aL = bufb + BUF_SPLIT + laneoff;
        float xi0 = xiT[d*128 + ew + r];
        float xi1 = xiT[d*128 + ew + r + 8];

        #pragma unroll
        for (int ntp = 0; ntp < 8; ++ntp) {
            float vh[8] = {0,0,0,0,0,0,0,0};
            float vl[8] = {0,0,0,0,0,0,0,0};
            uint32_t rowoff = (uint32_t)ntp*16*ROWB;
            #pragma unroll
            for (int jt = 0; jt < 8; ++jt) {
                uint32_t bh[4], bl[4];
                ldsm4(bh, aH + rowoff + jt*32);
                ldsm4(bl, aL + rowoff + jt*32);
                mma_f16(vh,   Af[jt], bh,   vh);
                mma_f16(vh+4, Af[jt], bh+2, vh+4);
                mma_f16(vl,   Af[jt], bl,   vl);
                mma_f16(vl+4, Af[jt], bl+2, vl+4);
            }
            msg[2*ntp  ][0] += xi0*(vh[0] + LS*vl[0]);
            msg[2*ntp  ][1] += xi0*(vh[1] + LS*vl[1]);
            msg[2*ntp  ][2] += xi1*(vh[2] + LS*vl[2]);
            msg[2*ntp  ][3] += xi1*(vh[3] + LS*vl[3]);
            msg[2*ntp+1][0] += xi0*(vh[4] + LS*vl[4]);
            msg[2*ntp+1][1] += xi0*(vh[5] + LS*vl[5]);
            msg[2*ntp+1][2] += xi1*(vh[6] + LS*vl[6]);
            msg[2*ntp+1][3] += xi1*(vh[7] + LS*vl[7]);
        }
        __syncthreads();
    }

    int d0 = sDst[ew + r], d1 = sDst[ew + r + 8];
    #pragma unroll
    for (int nt = 0; nt < 16; ++nt) {
        int k = nt*8 + cq;
        atomicAdd(&g_msgsum[(size_t)d0*128 + k],     msg[nt][0]);
        atomicAdd(&g_msgsum[(size_t)d0*128 + k + 1], msg[nt][1]);
        atomicAdd(&g_msgsum[(size_t)d1*128 + k],     msg[nt][2]);
        atomicAdd(&g_msgsum[(size_t)d1*128 + k + 1], msg[nt][3]);
    }
}

__global__ void gru_kernel(const float* __restrict__ h0, float* __restrict__ out, int twice)
{
    int i = blockIdx.x*256 + threadIdx.x;
    if (i >= Ng*Dg) return;
    int n = i>>7, k = i&127;
    const float* gir = g_gi + (size_t)n*384;
    const float* ghr = g_gh + (size_t)n*384;
    float r = 1.f/(1.f + expf(-(gir[k]     + ghr[k])));
    float z = 1.f/(1.f + expf(-(gir[128+k] + ghr[128+k])));
    float nn = tanhf(gir[256+k] + r*ghr[256+k]);
    float hn = (1.f - z)*nn + z*h0[i];
    out[i] = hn;
    if (twice) out[Ng*Dg + i] = hn;
}

static float* sym(const void* s) { void* p=0; cudaGetSymbolAddress(&p, s); return (float*)p; }
static unsigned short* symu(const void* s) { void* p=0; cudaGetSymbolAddress(&p, s); return (unsigned short*)p; }

extern "C" void kernel_launch(void* const* d_in, const int* in_sizes, int n_in,
                              void* d_out, int out_size)
{
    const float* node   = (const float*)d_in[0];
    const int*   ei     = (const int*)  d_in[1];
    const float* edge   = (const float*)d_in[2];
    const float* hidden = (const float*)d_in[3];
    const float* W1=(const float*)d_in[4],  *g1=(const float*)d_in[5],  *b1=(const float*)d_in[6];
    const float* W2=(const float*)d_in[7],  *g2=(const float*)d_in[8],  *b2=(const float*)d_in[9];
    const float* W3=(const float*)d_in[10], *g3=(const float*)d_in[11], *b3=(const float*)d_in[12];
    const float* W4=(const float*)d_in[13];
    const float* g4=(const float*)d_in[14], *b4=(const float*)d_in[15];
    const float* bias=(const float*)d_in[16];
    const float* W_ih=(const float*)d_in[17], *W_hh=(const float*)d_in[18];
    const float* b_ih=(const float*)d_in[19], *b_hh=(const float*)d_in[20];
    (void)in_sizes; (void)n_in;

    float *x1=sym(g_x1), *x2=sym(g_x2), *x3=sym(g_x3), *U=sym(g_U);
    float *ps1=sym(g_ps1), *pq1=sym(g_pq1), *ps2=sym(g_ps2), *pq2=sym(g_pq2);
    float *ps3=sym(g_ps3), *pq3=sym(g_pq3);
    float *mr=sym(g_mrelu), *gi=sym(g_gi), *gh=sym(g_gh), *S=sym(g_S);
    unsigned short *W1h=symu(g_W1h), *W1l=symu(g_W1l);
    unsigned short *W2h=symu(g_W2h), *W2l=symu(g_W2l);
    unsigned short *W3h=symu(g_W3h), *W3l=symu(g_W3l);
    unsigned short *Wihh=symu(g_Wihh), *Wihl=symu(g_Wihl);
    unsigned short *Whhh=symu(g_Whhh), *Whhl=symu(g_Whhl);
    unsigned short *C3h=symu(g_C3h), *C3l=symu(g_C3l);
    unsigned short *bTh=symu(g_bTh), *bTl=symu(g_bTl);

    cudaFuncSetAttribute(hgemm, cudaFuncAttributeMaxDynamicSharedMemorySize, H_SMEM);
    cudaFuncSetAttribute(big_msg_kernel, cudaFuncAttributeMaxDynamicSharedMemorySize, BIG_SMEM);

    zero_kernel<<<2048,256>>>();
    wsplit_kernel<<<784,256>>>(W1, W2, W3, W_ih, W_hh);
    ssum_kernel<<<Eg*128/256,256>>>(ei, node);

    // layer 1: x1 = edge @ W1^T (raw) + stats
    hgemm<<<dim3(2,128),256,H_SMEM>>>(edge, W1h, W1l, x1, nullptr, Eg, 256, 16,
        0, nullptr,nullptr,nullptr,nullptr, 0.f, 1, ps1, pq1);
    // layer 2: A = bnrelu(x1), stats -> ps2
    hgemm<<<dim3(2,128),256,H_SMEM>>>(x1, W2h, W2l, x2, nullptr, Eg, 256, 256,
        1, ps1, pq1, g1, b1, 1.f/Eg, 1, ps2, pq2);
    // layer 3: A = bnrelu(x2), stats -> ps3 (raw x3)
    hgemm<<<dim3(1,128),256,H_SMEM>>>(x2, W3h, W3l, x3, nullptr, Eg, 128, 256,
        1, ps2, pq2, g2, b2, 1.f/Eg, 1, ps3, pq3);

    bnx3_kernel<<<128,256>>>(g3, b3);
    syrk_x3<<<dim3(16,32),256>>>();
    csplit_kernel<<<64,256>>>();
    // U = W4 @ C3
    hgemm<<<dim3(1,128),256,H_SMEM>>>(W4, C3h, C3l, U, nullptr, DD, 128, 128,
        0, nullptr,nullptr,nullptr,nullptr, 0.f, 0, nullptr, nullptr);
    alphabeta_kernel<<<64,256>>>(W4, g4, b4);
    gsplit_kernel<<<DD*128/256,256>>>(W4);

    big_msg_kernel<<<128,256,BIG_SMEM>>>(node, ei);

    // sbeta GEMM fused with message finalize -> mrelu
    hgemm<<<dim3(1,32),256,H_SMEM>>>(S, bTh, bTl, mr, bias, Ng, 128, 128,
        0, nullptr,nullptr,nullptr,nullptr, 0.f, 2, nullptr, nullptr);

    hgemm<<<dim3(3,32),256,H_SMEM>>>(mr,     Wihh, Wihl, gi, b_ih, Ng, 384, 128,
        0, nullptr,nullptr,nullptr,nullptr, 0.f, 0, nullptr, nullptr);
    hgemm<<<dim3(3,32),256,H_SMEM>>>(hidden, Whhh, Whhl, gh, b_hh, Ng, 384, 128,
        0, nullptr,nullptr,nullptr,nullptr, 0.f, 0, nullptr, nullptr);

    int twice = (out_size >= 2*Ng*Dg) ? 1 : 0;
    gru_kernel<<<2048,256>>>(hidden, (float*)d_out, twice);
}

// round 8
// speedup vs baseline: 5.3194x; 1.4581x over previous
#include <cuda_runtime.h>
#include <cuda_bf16.h>
#include <cuda_fp16.h>
#include <cstdint>

#define Eg 16384
#define Ng 4096
#define Dg 128
#define DD 16384

static __device__ float g_x1[Eg*256];
static __device__ float g_x2[Eg*256];
static __device__ float g_x3[Eg*Dg];
static __device__ float g_U[DD*Dg];
static __device__ float g_C3[Dg*Dg];
static __device__ float g_alpha[DD];
static __device__ float g_ps1[256], g_pq1[256];
static __device__ float g_ps2[256], g_pq2[256];
static __device__ float g_ps3[128], g_pq3[128];
static __device__ float g_mx3sum[128];
static __device__ float g_msgsum[Ng*Dg];
static __device__ float g_S[Ng*Dg];
static __device__ float g_cnt[Ng];
static __device__ float g_mrelu[Ng*Dg];
static __device__ float g_gi[Ng*384];
static __device__ float g_gh[Ng*384];
static __device__ unsigned short g_Gh[DD*128];
// presplit weights (bf16 hi/lo)
static __device__ unsigned short g_W1h[4096],   g_W1l[4096];
static __device__ unsigned short g_W2h[65536],  g_W2l[65536];
static __device__ unsigned short g_W3h[32768],  g_W3l[32768];
static __device__ unsigned short g_Wihh[49152], g_Wihl[49152];
static __device__ unsigned short g_Whhh[49152], g_Whhl[49152];
static __device__ unsigned short g_C3h[16384],  g_C3l[16384];
static __device__ unsigned short g_bTh[16384],  g_bTl[16384];

// ---------- helpers ----------
__device__ __forceinline__ uint32_t smem_u32(const void* p) {
    uint32_t a;
    asm("{ .reg .u64 t; cvta.to.shared.u64 t, %1; cvt.u32.u64 %0, t; }" : "=r"(a) : "l"(p));
    return a;
}
__device__ __forceinline__ void mma_bf16(float* d, const uint32_t* a, const uint32_t* b, const float* c) {
    asm volatile("mma.sync.aligned.m16n8k16.row.col.f32.bf16.bf16.f32 "
        "{%0,%1,%2,%3}, {%4,%5,%6,%7}, {%8,%9}, {%10,%11,%12,%13};"
        : "=f"(d[0]),"=f"(d[1]),"=f"(d[2]),"=f"(d[3])
        : "r"(a[0]),"r"(a[1]),"r"(a[2]),"r"(a[3]), "r"(b[0]),"r"(b[1]),
          "f"(c[0]),"f"(c[1]),"f"(c[2]),"f"(c[3]));
}
__device__ __forceinline__ void mma_f16(float* d, const uint32_t* a, const uint32_t* b, const float* c) {
    asm volatile("mma.sync.aligned.m16n8k16.row.col.f32.f16.f16.f32 "
        "{%0,%1,%2,%3}, {%4,%5,%6,%7}, {%8,%9}, {%10,%11,%12,%13};"
        : "=f"(d[0]),"=f"(d[1]),"=f"(d[2]),"=f"(d[3])
        : "r"(a[0]),"r"(a[1]),"r"(a[2]),"r"(a[3]), "r"(b[0]),"r"(b[1]),
          "f"(c[0]),"f"(c[1]),"f"(c[2]),"f"(c[3]));
}
__device__ __forceinline__ void ldsm4(uint32_t* r, uint32_t addr) {
    asm volatile("ldmatrix.sync.aligned.m8n8.x4.shared.b16 {%0,%1,%2,%3}, [%4];"
        : "=r"(r[0]),"=r"(r[1]),"=r"(r[2]),"=r"(r[3]) : "r"(addr));
}
__device__ __forceinline__ void cp16(uint32_t dst, const void* src) {
    asm volatile("cp.async.cg.shared.global [%0], [%1], 16;" :: "r"(dst), "l"(src));
}
#define CP_COMMIT() asm volatile("cp.async.commit_group;" ::: "memory")
__device__ __forceinline__ uint32_t f2h2(float2 p) {
    __half2 h = __float22half2_rn(p);
    return *(uint32_t*)&h;
}
__device__ __forceinline__ void split2(float2 p, uint32_t& hi, uint32_t& lo) {
    uint32_t u0=__float_as_uint(p.x), u1=__float_as_uint(p.y);
    hi = __byte_perm(u0,u1,0x7632);
    float h0=__uint_as_float(u0&0xFFFF0000u), h1=__uint_as_float(u1&0xFFFF0000u);
    __nv_bfloat162 l2=__floats2bfloat162_rn(p.x-h0,p.y-h1);
    lo = *(uint32_t*)&l2;
}

// ---------- weight presplit ----------
__global__ void wsplit_kernel(const float* W1, const float* W2, const float* W3,
                              const float* Wih, const float* Whh)
{
    int i = blockIdx.x*256 + threadIdx.x;   // < 200704
    const float* src; unsigned short *dh, *dl; int off;
    if (i < 4096)        { src=W1;  dh=g_W1h;  dl=g_W1l;  off=i; }
    else if (i < 69632)  { src=W2;  dh=g_W2h;  dl=g_W2l;  off=i-4096; }
    else if (i < 102400) { src=W3;  dh=g_W3h;  dl=g_W3l;  off=i-69632; }
    else if (i < 151552) { src=Wih; dh=g_Wihh; dl=g_Wihl; off=i-102400; }
    else                 { src=Whh; dh=g_Whhh; dl=g_Whhl; off=i-151552; }
    float v = src[off];
    uint32_t u = __float_as_uint(v);
    dh[off] = (unsigned short)(u>>16);
    __nv_bfloat16 lb = __float2bfloat16_rn(v - __uint_as_float(u & 0xFFFF0000u));
    dl[off] = *(unsigned short*)&lb;
}
__global__ void csplit_kernel()
{
    int i = blockIdx.x*256 + threadIdx.x;
    float v = g_C3[i];
    uint32_t u = __float_as_uint(v);
    g_C3h[i] = (unsigned short)(u>>16);
    __nv_bfloat16 lb = __float2bfloat16_rn(v - __uint_as_float(u & 0xFFFF0000u));
    g_C3l[i] = *(unsigned short*)&lb;
}

// ---------- unified tensor-core GEMM (unchanged from R7 pass) ----------
#define SA_OFF(s)  ((s)*10240)
#define SBH_OFF(s) (20480 + (s)*12288)
#define SBL_OFF(s) (20480 + (s)*12288 + 6144)
#define SSC_OFF    45056
#define SSH_OFF    46080
#define H_SMEM     47104

__global__ __launch_bounds__(256) void hgemm(
    const float* __restrict__ A,
    const unsigned short* __restrict__ Bh, const unsigned short* __restrict__ Bl,
    float* __restrict__ C, const float* __restrict__ bias,
    int M, int Nc, int K,
    int amode, const float* __restrict__ psA, const float* __restrict__ pqA,
    const float* __restrict__ gA, const float* __restrict__ bA, float invE,
    int emode, float* __restrict__ psO, float* __restrict__ pqO)
{
    extern __shared__ char sm[];
    uint32_t smb = smem_u32(sm);
    float* sScale = (float*)(sm + SSC_OFF);
    float* sShift = (float*)(sm + SSH_OFF);
    int tid = threadIdx.x, l = tid&31, wid = tid>>5;
    int m0 = blockIdx.y*128, n0 = blockIdx.x*128;
    int wm = (wid>>1)*32, wn = (wid&1)*64;
    int r = l>>2, c2 = (l&3)*2;
    int ln = ((l>>4)&1)*8 + (l&7);
    int colsel = (l>>3)&1;

    if (amode) {
        for (int c = tid; c < K; c += 256) {
            float m = psA[c]*invE;
            float var = pqA[c]*invE - m*m;
            float sc = rsqrtf(var + 1e-5f) * gA[c];
            sScale[c] = sc;
            sShift[c] = bA[c] - m*sc;
        }
    }

    float acc[2][8][4];
    #pragma unroll
    for (int mf=0;mf<2;++mf)
        #pragma unroll
        for (int nf=0;nf<8;++nf) { acc[mf][nf][0]=0;acc[mf][nf][1]=0;acc[mf][nf][2]=0;acc[mf][nf][3]=0; }

    int steps = K>>4;
    {
        #pragma unroll
        for (int i=0;i<2;++i) {
            int q = tid + i*256, row = q>>2, c4 = q&3;
            cp16(smb + SA_OFF(0) + row*80 + c4*16, A + (size_t)(m0+row)*K + c4*4);
        }
        int row = tid>>1, c = tid&1;
        cp16(smb + SBH_OFF(0) + row*48 + c*16, Bh + (size_t)(n0+row)*K + c*8);
        cp16(smb + SBL_OFF(0) + row*48 + c*16, Bl + (size_t)(n0+row)*K + c*8);
        CP_COMMIT();
    }

    for (int s=0; s<steps; ++s) {
        if (s+1 < steps) {
            int b = (s+1)&1, k0 = (s+1)*16;
            #pragma unroll
            for (int i=0;i<2;++i) {
                int q = tid + i*256, row = q>>2, c4 = q&3;
                cp16(smb + SA_OFF(b) + row*80 + c4*16, A + (size_t)(m0+row)*K + k0 + c4*4);
            }
            int row = tid>>1, c = tid&1;
            cp16(smb + SBH_OFF(b) + row*48 + c*16, Bh + (size_t)(n0+row)*K + k0 + c*8);
            cp16(smb + SBL_OFF(b) + row*48 + c*16, Bl + (size_t)(n0+row)*K + k0 + c*8);
            CP_COMMIT();
            asm volatile("cp.async.wait_group 1;" ::: "memory");
        } else {
            asm volatile("cp.async.wait_group 0;" ::: "memory");
        }
        __syncthreads();

        const float* a_ = (const float*)(sm + SA_OFF(s&1));
        int k0 = s*16;
        uint32_t Ah[2][4], Al[2][4];
        #pragma unroll
        for (int mf=0;mf<2;++mf) {
            const float* r0 = a_ + (wm+mf*16+r)*20;
            const float* r1 = a_ + (wm+mf*16+r+8)*20;
            float2 p[4];
            p[0]=*(const float2*)&r0[c2];   p[1]=*(const float2*)&r1[c2];
            p[2]=*(const float2*)&r0[c2+8]; p[3]=*(const float2*)&r1[c2+8];
            if (amode) {
                float sc0=sScale[k0+c2], sc1=sScale[k0+c2+1];
                float sh0=sShift[k0+c2], sh1=sShift[k0+c2+1];
                float sc2=sScale[k0+c2+8], sc3=sScale[k0+c2+9];
                float sh2=sShift[k0+c2+8], sh3=sShift[k0+c2+9];
                p[0].x=fmaxf(p[0].x*sc0+sh0,0.f); p[0].y=fmaxf(p[0].y*sc1+sh1,0.f);
                p[1].x=fmaxf(p[1].x*sc0+sh0,0.f); p[1].y=fmaxf(p[1].y*sc1+sh1,0.f);
                p[2].x=fmaxf(p[2].x*sc2+sh2,0.f); p[2].y=fmaxf(p[2].y*sc3+sh3,0.f);
                p[3].x=fmaxf(p[3].x*sc2+sh2,0.f); p[3].y=fmaxf(p[3].y*sc3+sh3,0.f);
            }
            #pragma unroll
            for (int q=0;q<4;++q) split2(p[q], Ah[mf][q], Al[mf][q]);
        }
        uint32_t bh4[4][4], bl4[4][4];
        #pragma unroll
        for (int i=0;i<4;++i) {
            uint32_t boff = (uint32_t)(wn + 16*i + ln)*48 + colsel*16;
            ldsm4(bh4[i], smb + SBH_OFF(s&1) + boff);
            ldsm4(bl4[i], smb + SBL_OFF(s&1) + boff);
        }
        __syncthreads();

        #pragma unroll
        for (int mf=0;mf<2;++mf)
            #pragma unroll
            for (int nf=0;nf<8;++nf) {
                const uint32_t* bh = &bh4[nf>>1][(nf&1)*2];
                const uint32_t* bl = &bl4[nf>>1][(nf&1)*2];
                mma_bf16(acc[mf][nf], Ah[mf], bh, acc[mf][nf]);
                mma_bf16(acc[mf][nf], Al[mf], bh, acc[mf][nf]);
                mma_bf16(acc[mf][nf], Ah[mf], bl, acc[mf][nf]);
            }
    }

    if (emode == 2) {
        #pragma unroll
        for (int mf=0;mf<2;++mf) {
            int row0 = m0+wm+mf*16+r;
            float cn0 = fmaxf(g_cnt[row0],1.f), cn1 = fmaxf(g_cnt[row0+8],1.f);
            #pragma unroll
            for (int nf=0;nf<8;++nf) {
                int col = n0+wn+nf*8+c2;
                float2 bv = *(const float2*)&bias[col];
                float2 m0v = *(const float2*)&g_msgsum[(size_t)row0*Nc + col];
                float2 m1v = *(const float2*)&g_msgsum[(size_t)(row0+8)*Nc + col];
                float2 o0, o1;
                o0.x = fmaxf((acc[mf][nf][0]+m0v.x)/cn0 + bv.x, 0.f);
                o0.y = fmaxf((acc[mf][nf][1]+m0v.y)/cn0 + bv.y, 0.f);
                o1.x = fmaxf((acc[mf][nf][2]+m1v.x)/cn1 + bv.x, 0.f);
                o1.y = fmaxf((acc[mf][nf][3]+m1v.y)/cn1 + bv.y, 0.f);
                *(float2*)&C[(size_t)row0*Nc + col]     = o0;
                *(float2*)&C[(size_t)(row0+8)*Nc + col] = o1;
            }
        }
        return;
    }
    #pragma unroll
    for (int mf=0;mf<2;++mf) {
        int row0 = m0+wm+mf*16+r;
        #pragma unroll
        for (int nf=0;nf<8;++nf) {
            int col = n0+wn+nf*8+c2;
            float2 o0 = make_float2(acc[mf][nf][0], acc[mf][nf][1]);
            float2 o1 = make_float2(acc[mf][nf][2], acc[mf][nf][3]);
            if (bias) {
                float2 bv = *(const float2*)&bias[col];
                o0.x+=bv.x; o0.y+=bv.y; o1.x+=bv.x; o1.y+=bv.y;
            }
            *(float2*)&C[(size_t)row0*Nc + col]     = o0;
            *(float2*)&C[(size_t)(row0+8)*Nc + col] = o1;
        }
    }
    if (emode == 1) {
        #pragma unroll
        for (int nf=0;nf<8;++nf) {
            float s0=0,s1=0,q0=0,q1=0;
            #pragma unroll
            for (int mf=0;mf<2;++mf) {
                float a0=acc[mf][nf][0], a1=acc[mf][nf][1], a2=acc[mf][nf][2], a3=acc[mf][nf][3];
                s0+=a0+a2; s1+=a1+a3; q0+=a0*a0+a2*a2; q1+=a1*a1+a3*a3;
            }
            #pragma unroll
            for (int st=4; st<32; st<<=1) {
                s0 += __shfl_xor_sync(0xFFFFFFFF, s0, st);
                s1 += __shfl_xor_sync(0xFFFFFFFF, s1, st);
                q0 += __shfl_xor_sync(0xFFFFFFFF, q0, st);
                q1 += __shfl_xor_sync(0xFFFFFFFF, q1, st);
            }
            if (l < 4) {
                int col = n0+wn+nf*8+c2;
                atomicAdd(&psO[col], s0);   atomicAdd(&psO[col+1], s1);
                atomicAdd(&pqO[col], q0);   atomicAdd(&pqO[col+1], q1);
            }
        }
    }
}

// ---------- x3 BN+relu materialize + column sums ----------
__global__ __launch_bounds__(256) void bnx3_kernel(
    const float* __restrict__ g3, const float* __restrict__ b3)
{
    __shared__ float scol[256];
    int tid = threadIdx.x;
    int col = tid & 127, half = tid >> 7;
    float m = g_ps3[col]*(1.f/Eg);
    float var = g_pq3[col]*(1.f/Eg) - m*m;
    float sc = rsqrtf(var+1e-5f)*g3[col];
    float sh = b3[col] - m*sc;
    int r0 = blockIdx.x*128 + half;
    float s = 0.f;
    for (int i = 0; i < 64; ++i) {
        size_t idx = (size_t)(r0 + 2*i)*128 + col;
        float v = fmaxf(g_x3[idx]*sc + sh, 0.f);
        g_x3[idx] = v;
        s += v;
    }
    scol[tid] = s;
    __syncthreads();
    if (half == 0) atomicAdd(&g_mx3sum[col], scol[col] + scol[col+128]);
}

__global__ __launch_bounds__(256) void syrk_x3()
{
    __shared__ float sAcc[8][1024];
    int tid = threadIdx.x, lane = tid&31, w = tid>>5;
    int i0 = blockIdx.x*8;
    int seg = Eg/gridDim.y, e0 = blockIdx.y*seg, e1 = e0+seg;
    float acc[8][4];
    #pragma unroll
    for (int a=0;a<8;++a){acc[a][0]=0;acc[a][1]=0;acc[a][2]=0;acc[a][3]=0;}
    for (int e=e0+w; e<e1; e+=8) {
        const float* row = g_x3 + (size_t)e*128;
        float4 xj = *(const float4*)&row[lane*4];
        float4 x0 = *(const float4*)&row[i0];
        float4 x1 = *(const float4*)&row[i0+4];
        float xi[8]={x0.x,x0.y,x0.z,x0.w,x1.x,x1.y,x1.z,x1.w};
        float xv[4]={xj.x,xj.y,xj.z,xj.w};
        #pragma unroll
        for (int a=0;a<8;++a)
            #pragma unroll
            for (int b=0;b<4;++b) acc[a][b]+=xi[a]*xv[b];
    }
    #pragma unroll
    for (int a=0;a<8;++a)
        *(float4*)&sAcc[w][a*128+lane*4]=make_float4(acc[a][0],acc[a][1],acc[a][2],acc[a][3]);
    __syncthreads();
    for (int o=tid;o<1024;o+=256) {
        float s=0.f;
        #pragma unroll
        for (int ww=0;ww<8;++ww) s+=sAcc[ww][o];
        atomicAdd(&g_C3[(i0+(o>>7))*128 + (o&127)], s);
    }
}
__global__ void alphabeta_kernel(const float* __restrict__ W4,
    const float* __restrict__ g4, const float* __restrict__ b4)
{
    int c = blockIdx.x*blockDim.x + threadIdx.x;
    const float4* w = (const float4*)(W4 + (size_t)c*128);
    const float4* u = (const float4*)(g_U + (size_t)c*128);
    const float4* mx = (const float4*)g_mx3sum;
    float ms=0.f, q=0.f;
    #pragma unroll 8
    for (int i=0;i<32;++i) {
        float4 wv=w[i], uv=u[i], mv=mx[i];
        ms += wv.x*mv.x + wv.y*mv.y + wv.z*mv.z + wv.w*mv.w;
        q  += wv.x*uv.x + wv.y*uv.y + wv.z*uv.z + wv.w*uv.w;
    }
    float m4 = ms*(1.f/Eg);
    float var = q*(1.0f/(float)Eg) - m4*m4;
    float a = g4[c]*rsqrtf(var + 1e-5f);
    g_alpha[c]=a;
    float bv = b4[c]-m4*a;
    int t = (c&127)*128 + (c>>7);
    uint32_t uu = __float_as_uint(bv);
    g_bTh[t] = (unsigned short)(uu>>16);
    __nv_bfloat16 lb = __float2bfloat16_rn(bv - __uint_as_float(uu & 0xFFFF0000u));
    g_bTl[t] = *(unsigned short*)&lb;
}
__global__ void gsplit_kernel(const float* __restrict__ W4)
{
    int idx = blockIdx.x*256 + threadIdx.x;
    int c = idx >> 7;
    float v = g_alpha[c] * W4[idx];
    __half h = __float2half_rn(v);
    g_Gh[idx] = *(unsigned short*)&h;
}
__global__ void zero_kernel()
{
    int i = blockIdx.x*256 + threadIdx.x;
    if (i < Ng*Dg) { g_msgsum[i]=0.f; g_S[i]=0.f; }
    if (i < Ng)    g_cnt[i]=0.f;
    if (i < Dg*Dg) g_C3[i]=0.f;
    if (i < 256)   { g_ps1[i]=0.f; g_pq1[i]=0.f; g_ps2[i]=0.f; g_pq2[i]=0.f; }
    if (i < 128)   { g_ps3[i]=0.f; g_pq3[i]=0.f; g_mx3sum[i]=0.f; }
}
__global__ void ssum_kernel(const int* __restrict__ ei, const float* __restrict__ node)
{
    int idx = blockIdx.x*256 + threadIdx.x;
    if (idx >= Eg*128) return;
    int e = idx>>7, k = idx&127;
    int dst = ei[2*e+1];
    atomicAdd(&g_S[(size_t)dst*128 + k], node[(size_t)ei[2*e]*128 + k]);
    if (k == 0) atomicAdd(&g_cnt[dst], 1.0f);
}

// ---------- big fused GEMM: single-product fp16 ----------
#define ROWB   272
#define BUF_SIZE  (128*ROWB)          // 34816 (hi plane only)
#define XIT_OFF   (2*BUF_SIZE)        // 69632
#define BIG_SMEM  (XIT_OFF + 65536)   // 135168

__device__ __forceinline__ void load_G(int d, int tid, uint32_t smem_base) {
    const char* GH = (const char*)g_Gh;
    uint32_t bufb = smem_base + (d&1)*BUF_SIZE;
    #pragma unroll
    for (int i=0;i<8;++i) {
        int q = tid + i*256;            // 0..2047
        int row = q>>4, c16 = q&15;
        cp16(bufb + row*ROWB + c16*16, GH + ((size_t)d*128 + row)*256 + c16*16);
    }
    CP_COMMIT();
}

__global__ __launch_bounds__(256,1) void big_msg_kernel(
    const float* __restrict__ node, const int* __restrict__ ei)
{
    extern __shared__ char sm[];
    float* xiT = (float*)(sm + XIT_OFF);
    __shared__ int sDst[128];
    int tid = threadIdx.x, l = tid&31, w = tid>>5;
    int e0 = blockIdx.x*128;
    {
        int e = tid>>1, hf = tid&1;
        int src = ei[2*(e0+e)];
        if (hf==0) sDst[e] = ei[2*(e0+e)+1];
        const float* nr = node + (size_t)src*128 + hf*64;
        #pragma unroll
        for (int i=0;i<16;++i) {
            float4 v = *(const float4*)&nr[i*4];
            int d = hf*64 + i*4;
            xiT[(d+0)*128+e]=v.x; xiT[(d+1)*128+e]=v.y; xiT[(d+2)*128+e]=v.z; xiT[(d+3)*128+e]=v.w;
        }
    }
    float* sx3 = (float*)sm;   // temp (fits in 2 buffers = 69632 > 65536)
    {
        const float* xr = g_x3 + (size_t)e0*128;
        #pragma unroll
        for (int i=0;i<16;++i) {
            int u = tid + i*256;
            *(float4*)&sx3[u*4] = *(const float4*)&xr[u*4];
        }
    }
    __syncthreads();
    int ew = w*16;
    int r = l>>2, cq = (l&3)*2;
    uint32_t Af[8][4];
    {
        const float* Xr0 = sx3 + (size_t)(ew + r)*128;
        const float* Xr1 = sx3 + (size_t)(ew + r + 8)*128;
        #pragma unroll
        for (int jt=0;jt<8;++jt) {
            int c0 = jt*16 + cq;
            Af[jt][0] = f2h2(*(const float2*)&Xr0[c0]);
            Af[jt][1] = f2h2(*(const float2*)&Xr1[c0]);
            Af[jt][2] = f2h2(*(const float2*)&Xr0[c0+8]);
            Af[jt][3] = f2h2(*(const float2*)&Xr1[c0+8]);
        }
    }
    __syncthreads();

    uint32_t smem_base = smem_u32(sm);
    int ln = ((l>>4)&1)*8 + (l&7);
    int colsel = (l>>3)&1;
    uint32_t laneoff = (uint32_t)ln*ROWB + colsel*16;

    float msg[16][4];
    #pragma unroll
    for (int nt=0;nt<16;++nt) { msg[nt][0]=0;msg[nt][1]=0;msg[nt][2]=0;msg[nt][3]=0; }

    load_G(0, tid, smem_base);

    for (int d = 0; d < 128; ++d) {
        if (d < 127) {
            load_G(d+1, tid, smem_base);
            asm volatile("cp.async.wait_group 1;" ::: "memory");
        } else {
            asm volatile("cp.async.wait_group 0;" ::: "memory");
        }
        __syncthreads();

        uint32_t aH = smem_base + (d&1)*BUF_SIZE + laneoff;
        float xi0 = xiT[d*128 + ew + r];
        float xi1 = xiT[d*128 + ew + r + 8];

        #pragma unroll
        for (int ntp = 0; ntp < 8; ++ntp) {
            float vh[8] = {0,0,0,0,0,0,0,0};
            uint32_t rowoff = (uint32_t)ntp*16*ROWB;
            #pragma unroll
            for (int jt = 0; jt < 8; ++jt) {
                uint32_t bh[4];
                ldsm4(bh, aH + rowoff + jt*32);
                mma_f16(vh,   Af[jt], bh,   vh);
                mma_f16(vh+4, Af[jt], bh+2, vh+4);
            }
            msg[2*ntp  ][0] += xi0*vh[0];
            msg[2*ntp  ][1] += xi0*vh[1];
            msg[2*ntp  ][2] += xi1*vh[2];
            msg[2*ntp  ][3] += xi1*vh[3];
            msg[2*ntp+1][0] += xi0*vh[4];
            msg[2*ntp+1][1] += xi0*vh[5];
            msg[2*ntp+1][2] += xi1*vh[6];
            msg[2*ntp+1][3] += xi1*vh[7];
        }
        __syncthreads();
    }

    int d0 = sDst[ew + r], d1 = sDst[ew + r + 8];
    #pragma unroll
    for (int nt = 0; nt < 16; ++nt) {
        int k = nt*8 + cq;
        atomicAdd(&g_msgsum[(size_t)d0*128 + k],     msg[nt][0]);
        atomicAdd(&g_msgsum[(size_t)d0*128 + k + 1], msg[nt][1]);
        atomicAdd(&g_msgsum[(size_t)d1*128 + k],     msg[nt][2]);
        atomicAdd(&g_msgsum[(size_t)d1*128 + k + 1], msg[nt][3]);
    }
}

__global__ void gru_kernel(const float* __restrict__ h0, float* __restrict__ out, int twice)
{
    int i = blockIdx.x*256 + threadIdx.x;
    if (i >= Ng*Dg) return;
    int n = i>>7, k = i&127;
    const float* gir = g_gi + (size_t)n*384;
    const float* ghr = g_gh + (size_t)n*384;
    float r = 1.f/(1.f + expf(-(gir[k]     + ghr[k])));
    float z = 1.f/(1.f + expf(-(gir[128+k] + ghr[128+k])));
    float nn = tanhf(gir[256+k] + r*ghr[256+k]);
    float hn = (1.f - z)*nn + z*h0[i];
    out[i] = hn;
    if (twice) out[Ng*Dg + i] = hn;
}

static float* sym(const void* s) { void* p=0; cudaGetSymbolAddress(&p, s); return (float*)p; }
static unsigned short* symu(const void* s) { void* p=0; cudaGetSymbolAddress(&p, s); return (unsigned short*)p; }

extern "C" void kernel_launch(void* const* d_in, const int* in_sizes, int n_in,
                              void* d_out, int out_size)
{
    const float* node   = (const float*)d_in[0];
    const int*   ei     = (const int*)  d_in[1];
    const float* edge   = (const float*)d_in[2];
    const float* hidden = (const float*)d_in[3];
    const float* W1=(const float*)d_in[4],  *g1=(const float*)d_in[5],  *b1=(const float*)d_in[6];
    const float* W2=(const float*)d_in[7],  *g2=(const float*)d_in[8],  *b2=(const float*)d_in[9];
    const float* W3=(const float*)d_in[10], *g3=(const float*)d_in[11], *b3=(const float*)d_in[12];
    const float* W4=(const float*)d_in[13];
    const float* g4=(const float*)d_in[14], *b4=(const float*)d_in[15];
    const float* bias=(const float*)d_in[16];
    const float* W_ih=(const float*)d_in[17], *W_hh=(const float*)d_in[18];
    const float* b_ih=(const float*)d_in[19], *b_hh=(const float*)d_in[20];
    (void)in_sizes; (void)n_in;

    float *x1=sym(g_x1), *x2=sym(g_x2), *x3=sym(g_x3), *U=sym(g_U);
    float *ps1=sym(g_ps1), *pq1=sym(g_pq1), *ps2=sym(g_ps2), *pq2=sym(g_pq2);
    float *ps3=sym(g_ps3), *pq3=sym(g_pq3);
    float *mr=sym(g_mrelu), *gi=sym(g_gi), *gh=sym(g_gh), *S=sym(g_S);
    unsigned short *W1h=symu(g_W1h), *W1l=symu(g_W1l);
    unsigned short *W2h=symu(g_W2h), *W2l=symu(g_W2l);
    unsigned short *W3h=symu(g_W3h), *W3l=symu(g_W3l);
    unsigned short *Wihh=symu(g_Wihh), *Wihl=symu(g_Wihl);
    unsigned short *Whhh=symu(g_Whhh), *Whhl=symu(g_Whhl);
    unsigned short *C3h=symu(g_C3h), *C3l=symu(g_C3l);
    unsigned short *bTh=symu(g_bTh), *bTl=symu(g_bTl);

    cudaFuncSetAttribute(hgemm, cudaFuncAttributeMaxDynamicSharedMemorySize, H_SMEM);
    cudaFuncSetAttribute(big_msg_kernel, cudaFuncAttributeMaxDynamicSharedMemorySize, BIG_SMEM);

    zero_kernel<<<2048,256>>>();
    wsplit_kernel<<<784,256>>>(W1, W2, W3, W_ih, W_hh);
    ssum_kernel<<<Eg*128/256,256>>>(ei, node);

    hgemm<<<dim3(2,128),256,H_SMEM>>>(edge, W1h, W1l, x1, nullptr, Eg, 256, 16,
        0, nullptr,nullptr,nullptr,nullptr, 0.f, 1, ps1, pq1);
    hgemm<<<dim3(2,128),256,H_SMEM>>>(x1, W2h, W2l, x2, nullptr, Eg, 256, 256,
        1, ps1, pq1, g1, b1, 1.f/Eg, 1, ps2, pq2);
    hgemm<<<dim3(1,128),256,H_SMEM>>>(x2, W3h, W3l, x3, nullptr, Eg, 128, 256,
        1, ps2, pq2, g2, b2, 1.f/Eg, 1, ps3, pq3);

    bnx3_kernel<<<128,256>>>(g3, b3);
    syrk_x3<<<dim3(16,32),256>>>();
    csplit_kernel<<<64,256>>>();
    hgemm<<<dim3(1,128),256,H_SMEM>>>(W4, C3h, C3l, U, nullptr, DD, 128, 128,
        0, nullptr,nullptr,nullptr,nullptr, 0.f, 0, nullptr, nullptr);
    alphabeta_kernel<<<64,256>>>(W4, g4, b4);
    gsplit_kernel<<<DD*128/256,256>>>(W4);

    big_msg_kernel<<<128,256,BIG_SMEM>>>(node, ei);

    hgemm<<<dim3(1,32),256,H_SMEM>>>(S, bTh, bTl, mr, bias, Ng, 128, 128,
        0, nullptr,nullptr,nullptr,nullptr, 0.f, 2, nullptr, nullptr);

    hgemm<<<dim3(3,32),256,H_SMEM>>>(mr,     Wihh, Wihl, gi, b_ih, Ng, 384, 128,
        0, nullptr,nullptr,nullptr,nullptr, 0.f, 0, nullptr, nullptr);
    hgemm<<<dim3(3,32),256,H_SMEM>>>(hidden, Whhh, Whhl, gh, b_hh, Ng, 384, 128,
        0, nullptr,nullptr,nullptr,nullptr, 0.f, 0, nullptr, nullptr);

    int twice = (out_size >= 2*Ng*Dg) ? 1 : 0;
    gru_kernel<<<2048,256>>>(hidden, (float*)d_out, twice);
}